// round 2
// baseline (speedup 1.0000x reference)
#include <cuda_runtime.h>
#include <math.h>

#define B_SZ   4
#define EDIM   256
#define N_TOK  4096
#define F3     768
#define SCL    0.0625f   // 1/sqrt(256)

// Scratch (allocation-free rule: __device__ globals)
__device__ float g_qkv[(size_t)B_SZ * N_TOK * F3];    // [b, n, 3E]
__device__ float g_obuf[(size_t)B_SZ * N_TOK * EDIM]; // [b, n, E]

__device__ __forceinline__ float warp_max16(float v) {
    v = fmaxf(v, __shfl_xor_sync(0xffffffffu, v, 1));
    v = fmaxf(v, __shfl_xor_sync(0xffffffffu, v, 2));
    v = fmaxf(v, __shfl_xor_sync(0xffffffffu, v, 4));
    v = fmaxf(v, __shfl_xor_sync(0xffffffffu, v, 8));
    return v;
}
__device__ __forceinline__ float warp_sum16(float v) {
    v += __shfl_xor_sync(0xffffffffu, v, 1);
    v += __shfl_xor_sync(0xffffffffu, v, 2);
    v += __shfl_xor_sync(0xffffffffu, v, 4);
    v += __shfl_xor_sync(0xffffffffu, v, 8);
    return v;
}

// ---------------------------------------------------------------------------
// Kernel 1: qkv[b, m, f] = sum_e x[b, e, m] * w[f, e] + bias[f]
// grid (N/64, F3/64, B), block 256.  Thread (tx,ty)=(tid%16, tid/16),
// computes rows m = ty*4+r, cols f = tx+16*c (4x4).
// ---------------------------------------------------------------------------
__global__ void qkv_kernel(const float* __restrict__ x,
                           const float* __restrict__ w,
                           const float* __restrict__ bias) {
    __shared__ float Xs[16][64];   // [e][m]
    __shared__ float Ws[64][17];   // [f][e]  (stride 17: conflict-free f-strided reads)
    const int tid = threadIdx.x;
    const int tx = tid & 15, ty = tid >> 4;
    const int mbase = blockIdx.x * 64;
    const int fbase = blockIdx.y * 64;
    const int b = blockIdx.z;
    const float* xb = x + (size_t)b * EDIM * N_TOK;

    float acc[4][4];
#pragma unroll
    for (int r = 0; r < 4; r++)
#pragma unroll
        for (int c = 0; c < 4; c++) acc[r][c] = 0.f;

    for (int e0 = 0; e0 < EDIM; e0 += 16) {
        __syncthreads();
        {   // Xs: 16 rows (e) x 64 cols (m) = 1024 floats; 1 float4/thread
            int e = tid >> 4, m4 = tid & 15;
            float4 v = *(const float4*)(xb + (size_t)(e0 + e) * N_TOK + mbase + m4 * 4);
            *(float4*)(&Xs[e][m4 * 4]) = v;
        }
        {   // Ws: 64 rows (f) x 16 cols (e); 1 float4/thread, scalar smem stores
            int f = tid >> 2, e4 = tid & 3;
            float4 v = *(const float4*)(w + (size_t)(fbase + f) * EDIM + e0 + e4 * 4);
            Ws[f][e4 * 4 + 0] = v.x; Ws[f][e4 * 4 + 1] = v.y;
            Ws[f][e4 * 4 + 2] = v.z; Ws[f][e4 * 4 + 3] = v.w;
        }
        __syncthreads();
#pragma unroll
        for (int e = 0; e < 16; e++) {
            float xr[4], wr[4];
#pragma unroll
            for (int r = 0; r < 4; r++) xr[r] = Xs[e][ty * 4 + r];
#pragma unroll
            for (int c = 0; c < 4; c++) wr[c] = Ws[tx + 16 * c][e];
#pragma unroll
            for (int r = 0; r < 4; r++)
#pragma unroll
                for (int c = 0; c < 4; c++) acc[r][c] += xr[r] * wr[c];
        }
    }

#pragma unroll
    for (int c = 0; c < 4; c++) {
        int f = fbase + tx + 16 * c;
        float bb = bias[f];
#pragma unroll
        for (int r = 0; r < 4; r++) {
            size_t m = (size_t)mbase + ty * 4 + r;
            g_qkv[((size_t)b * N_TOK + m) * F3 + f] = acc[r][c] + bb;
        }
    }
}

// ---------------------------------------------------------------------------
// Kernel 2: flash attention per (qtile of 64, batch).
// o[b, q, :] = softmax(q . k^T / 16) @ v   over all 4096 keys, D=256.
// Thread (tx,ty): S rows q = ty*4+r, S cols k = tx+16*c.
// O: 4 rows x 16 d-cols (d = g*64 + tx + 16*c).
// ---------------------------------------------------------------------------
__global__ __launch_bounds__(256, 2) void attn_kernel() {
    __shared__ float Qs[64][17];   // [q][dchunk16]
    __shared__ float Ks[64][17];   // [k][dchunk16]
    __shared__ float Ps[64][65];   // [q][k]
    __shared__ float Vs[64][68];   // [k][dchunk64]
    const int tid = threadIdx.x;
    const int tx = tid & 15, ty = tid >> 4;
    const int qbase = blockIdx.x * 64;
    const int b = blockIdx.y;
    const float* qkv = g_qkv + (size_t)b * N_TOK * F3;

    float O[4][16];
#pragma unroll
    for (int r = 0; r < 4; r++)
#pragma unroll
        for (int j = 0; j < 16; j++) O[r][j] = 0.f;
    float mrow[4] = {-INFINITY, -INFINITY, -INFINITY, -INFINITY};
    float lrow[4] = {0.f, 0.f, 0.f, 0.f};

    const int ldrow = tid >> 2, ldc4 = tid & 3;  // 64 rows x 1 float4

    for (int kb = 0; kb < N_TOK; kb += 64) {
        // ---- S = Q K^T over D=256 in chunks of 16 ----
        float S[4][4];
#pragma unroll
        for (int r = 0; r < 4; r++)
#pragma unroll
            for (int c = 0; c < 4; c++) S[r][c] = 0.f;

        for (int d0 = 0; d0 < EDIM; d0 += 16) {
            __syncthreads();
            {
                float4 v = *(const float4*)(qkv + (size_t)(qbase + ldrow) * F3 + d0 + ldc4 * 4);
                Qs[ldrow][ldc4 * 4 + 0] = v.x; Qs[ldrow][ldc4 * 4 + 1] = v.y;
                Qs[ldrow][ldc4 * 4 + 2] = v.z; Qs[ldrow][ldc4 * 4 + 3] = v.w;
                float4 u = *(const float4*)(qkv + (size_t)(kb + ldrow) * F3 + 256 + d0 + ldc4 * 4);
                Ks[ldrow][ldc4 * 4 + 0] = u.x; Ks[ldrow][ldc4 * 4 + 1] = u.y;
                Ks[ldrow][ldc4 * 4 + 2] = u.z; Ks[ldrow][ldc4 * 4 + 3] = u.w;
            }
            __syncthreads();
#pragma unroll
            for (int dc = 0; dc < 16; dc++) {
                float qr[4], kr[4];
#pragma unroll
                for (int r = 0; r < 4; r++) qr[r] = Qs[ty * 4 + r][dc];
#pragma unroll
                for (int c = 0; c < 4; c++) kr[c] = Ks[tx + 16 * c][dc];
#pragma unroll
                for (int r = 0; r < 4; r++)
#pragma unroll
                    for (int c = 0; c < 4; c++) S[r][c] += qr[r] * kr[c];
            }
        }

        // ---- online softmax (registers + shuffles only) ----
        float P[4][4];
#pragma unroll
        for (int r = 0; r < 4; r++) {
#pragma unroll
            for (int c = 0; c < 4; c++) S[r][c] *= SCL;
            float mm = fmaxf(fmaxf(S[r][0], S[r][1]), fmaxf(S[r][2], S[r][3]));
            mm = warp_max16(mm);
            float mnew = fmaxf(mrow[r], mm);
            float sc = __expf(mrow[r] - mnew);   // exp(-inf)=0 on first tile
            float rs = 0.f;
#pragma unroll
            for (int c = 0; c < 4; c++) {
                P[r][c] = __expf(S[r][c] - mnew);
                rs += P[r][c];
            }
            rs = warp_sum16(rs);
            lrow[r] = lrow[r] * sc + rs;
            mrow[r] = mnew;
#pragma unroll
            for (int j = 0; j < 16; j++) O[r][j] *= sc;
        }

        // ---- store P (prev-tile readers are past phase-A syncs) ----
#pragma unroll
        for (int r = 0; r < 4; r++)
#pragma unroll
            for (int c = 0; c < 4; c++) Ps[ty * 4 + r][tx + 16 * c] = P[r][c];

        // ---- O += P @ V, D in chunks of 64 ----
        for (int g = 0; g < 4; g++) {
            __syncthreads();   // also guards Ps stores (g==0) / Vs reuse (g>0)
#pragma unroll
            for (int i = 0; i < 4; i++) {
                int lin = tid + i * 256;
                int row = lin >> 4, c4 = lin & 15;
                float4 v = *(const float4*)(qkv + (size_t)(kb + row) * F3 + 512 + g * 64 + c4 * 4);
                *(float4*)(&Vs[row][c4 * 4]) = v;
            }
            __syncthreads();
#pragma unroll 8
            for (int nn = 0; nn < 64; nn++) {
                float pr[4], vr[4];
#pragma unroll
                for (int r = 0; r < 4; r++) pr[r] = Ps[ty * 4 + r][nn];
#pragma unroll
                for (int c = 0; c < 4; c++) vr[c] = Vs[nn][tx + 16 * c];
#pragma unroll
                for (int r = 0; r < 4; r++)
#pragma unroll
                    for (int c = 0; c < 4; c++) O[r][g * 4 + c] += pr[r] * vr[c];
            }
        }
    }

    // ---- normalize + write o ----
#pragma unroll
    for (int r = 0; r < 4; r++) {
        float inv = 1.f / lrow[r];
        size_t base = ((size_t)b * N_TOK + qbase + ty * 4 + r) * EDIM;
#pragma unroll
        for (int g = 0; g < 4; g++)
#pragma unroll
            for (int c = 0; c < 4; c++)
                g_obuf[base + g * 64 + tx + 16 * c] = O[r][g * 4 + c] * inv;
    }
}

// ---------------------------------------------------------------------------
// Kernel 3: out[b, e, m] = x[b, e, m] + sum_k out_w[e, k] * o[b, m, k] + out_b[e]
// grid (N/64, E/64, B), block 256. rows e = ty*4+r, cols m = tx+16*c.
// ---------------------------------------------------------------------------
__global__ void out_kernel(const float* __restrict__ x,
                           const float* __restrict__ w,
                           const float* __restrict__ bias,
                           float* __restrict__ out) {
    __shared__ float Ws[64][17];   // [e][k]
    __shared__ float Os[64][17];   // [m][k]
    const int tid = threadIdx.x;
    const int tx = tid & 15, ty = tid >> 4;
    const int mbase = blockIdx.x * 64;
    const int ebase = blockIdx.y * 64;
    const int b = blockIdx.z;

    float acc[4][4];
#pragma unroll
    for (int r = 0; r < 4; r++)
#pragma unroll
        for (int c = 0; c < 4; c++) acc[r][c] = 0.f;

    const int ldrow = tid >> 2, ldc4 = tid & 3;
    for (int k0 = 0; k0 < EDIM; k0 += 16) {
        __syncthreads();
        {
            float4 v = *(const float4*)(w + (size_t)(ebase + ldrow) * EDIM + k0 + ldc4 * 4);
            Ws[ldrow][ldc4 * 4 + 0] = v.x; Ws[ldrow][ldc4 * 4 + 1] = v.y;
            Ws[ldrow][ldc4 * 4 + 2] = v.z; Ws[ldrow][ldc4 * 4 + 3] = v.w;
            float4 u = *(const float4*)(g_obuf + ((size_t)b * N_TOK + mbase + ldrow) * EDIM + k0 + ldc4 * 4);
            Os[ldrow][ldc4 * 4 + 0] = u.x; Os[ldrow][ldc4 * 4 + 1] = u.y;
            Os[ldrow][ldc4 * 4 + 2] = u.z; Os[ldrow][ldc4 * 4 + 3] = u.w;
        }
        __syncthreads();
#pragma unroll
        for (int k = 0; k < 16; k++) {
            float wr[4], orr[4];
#pragma unroll
            for (int r = 0; r < 4; r++) wr[r] = Ws[ty * 4 + r][k];
#pragma unroll
            for (int c = 0; c < 4; c++) orr[c] = Os[tx + 16 * c][k];
#pragma unroll
            for (int r = 0; r < 4; r++)
#pragma unroll
                for (int c = 0; c < 4; c++) acc[r][c] += wr[r] * orr[c];
        }
    }

#pragma unroll
    for (int r = 0; r < 4; r++) {
        int e = ebase + ty * 4 + r;
        float bb = bias[e];
#pragma unroll
        for (int c = 0; c < 4; c++) {
            int m = mbase + tx + 16 * c;
            size_t idx = ((size_t)b * EDIM + e) * N_TOK + m;
            out[idx] = x[idx] + acc[r][c] + bb;
        }
    }
}

// ---------------------------------------------------------------------------
extern "C" void kernel_launch(void* const* d_in, const int* in_sizes, int n_in,
                              void* d_out, int out_size) {
    // Defensive: resolve inputs by element count (all five sizes are distinct).
    const float* x = nullptr; const float* qkv_w = nullptr; const float* qkv_b = nullptr;
    const float* out_w = nullptr; const float* out_b = nullptr;
    for (int i = 0; i < n_in; i++) {
        switch (in_sizes[i]) {
            case 4194304: x     = (const float*)d_in[i]; break; // 4*256*64*64
            case  196608: qkv_w = (const float*)d_in[i]; break; // 768*256
            case     768: qkv_b = (const float*)d_in[i]; break;
            case   65536: out_w = (const float*)d_in[i]; break; // 256*256
            case     256: out_b = (const float*)d_in[i]; break;
            default: break;
        }
    }
    float* out = (float*)d_out;

    qkv_kernel<<<dim3(N_TOK / 64, F3 / 64, B_SZ), 256>>>(x, qkv_w, qkv_b);
    attn_kernel<<<dim3(N_TOK / 64, B_SZ), 256>>>();
    out_kernel<<<dim3(N_TOK / 64, EDIM / 64, B_SZ), 256>>>(x, out_w, out_b, out);
}

// round 4
// speedup vs baseline: 1.9128x; 1.9128x over previous
#include <cuda_runtime.h>
#include <math.h>
#include <stdint.h>

#define B_SZ   4
#define EDIM   256
#define N_TOK  4096
#define F3     768
#define SCL    0.0625f   // 1/sqrt(256)

// Scratch (allocation-free rule: __device__ globals)
__device__ float g_qkv[(size_t)B_SZ * N_TOK * F3];    // [b, n, 3E]
__device__ float g_obuf[(size_t)B_SZ * N_TOK * EDIM]; // [b, n, E]

// tf32 cvt: destination must be a .b32 register in PTX
__device__ __forceinline__ uint32_t to_tf32(float x) {
    uint32_t r;
    asm("cvt.rna.tf32.f32 %0, %1;" : "=r"(r) : "f"(x));
    return r;
}
__device__ __forceinline__ float to_tf32f(float x) {
    return __uint_as_float(to_tf32(x));
}
__device__ __forceinline__ uint32_t f2u(float x) { return __float_as_uint(x); }

__device__ __forceinline__ void mma_tf32(float c[4],
                                         uint32_t a0, uint32_t a1, uint32_t a2, uint32_t a3,
                                         uint32_t b0, uint32_t b1) {
    asm volatile(
        "mma.sync.aligned.m16n8k8.row.col.f32.tf32.tf32.f32 "
        "{%0,%1,%2,%3}, {%4,%5,%6,%7}, {%8,%9}, {%0,%1,%2,%3};\n"
        : "+f"(c[0]), "+f"(c[1]), "+f"(c[2]), "+f"(c[3])
        : "r"(a0), "r"(a1), "r"(a2), "r"(a3), "r"(b0), "r"(b1));
}

// ---------------------------------------------------------------------------
// Kernel 1: qkv[b, m, f] = sum_e x[b, e, m] * w[f, e] + bias[f]  (SIMT fp32)
// ---------------------------------------------------------------------------
__global__ void qkv_kernel(const float* __restrict__ x,
                           const float* __restrict__ w,
                           const float* __restrict__ bias) {
    __shared__ float Xs[16][64];
    __shared__ float Ws[64][17];
    const int tid = threadIdx.x;
    const int tx = tid & 15, ty = tid >> 4;
    const int mbase = blockIdx.x * 64;
    const int fbase = blockIdx.y * 64;
    const int b = blockIdx.z;
    const float* xb = x + (size_t)b * EDIM * N_TOK;

    float acc[4][4];
#pragma unroll
    for (int r = 0; r < 4; r++)
#pragma unroll
        for (int c = 0; c < 4; c++) acc[r][c] = 0.f;

    for (int e0 = 0; e0 < EDIM; e0 += 16) {
        __syncthreads();
        {
            int e = tid >> 4, m4 = tid & 15;
            float4 v = *(const float4*)(xb + (size_t)(e0 + e) * N_TOK + mbase + m4 * 4);
            *(float4*)(&Xs[e][m4 * 4]) = v;
        }
        {
            int f = tid >> 2, e4 = tid & 3;
            float4 v = *(const float4*)(w + (size_t)(fbase + f) * EDIM + e0 + e4 * 4);
            Ws[f][e4 * 4 + 0] = v.x; Ws[f][e4 * 4 + 1] = v.y;
            Ws[f][e4 * 4 + 2] = v.z; Ws[f][e4 * 4 + 3] = v.w;
        }
        __syncthreads();
#pragma unroll
        for (int e = 0; e < 16; e++) {
            float xr[4], wr[4];
#pragma unroll
            for (int r = 0; r < 4; r++) xr[r] = Xs[e][ty * 4 + r];
#pragma unroll
            for (int c = 0; c < 4; c++) wr[c] = Ws[tx + 16 * c][e];
#pragma unroll
            for (int r = 0; r < 4; r++)
#pragma unroll
                for (int c = 0; c < 4; c++) acc[r][c] += xr[r] * wr[c];
        }
    }

#pragma unroll
    for (int c = 0; c < 4; c++) {
        int f = fbase + tx + 16 * c;
        float bb = bias[f];
#pragma unroll
        for (int r = 0; r < 4; r++) {
            size_t m = (size_t)mbase + ty * 4 + r;
            g_qkv[((size_t)b * N_TOK + m) * F3 + f] = acc[r][c] + bb;
        }
    }
}

// ---------------------------------------------------------------------------
// Kernel 2: flash attention, TF32 tensor cores.
// CTA: 64 q rows, 8 warps (256 thr). Per key tile of 64:
//   S phase : warp w computes S[16*(w&3)..+16, 32*(w>>2)..+32] via mma over d.
//   softmax : SIMT over Ps in smem, online m/l update (state in smem).
//   PV phase: warp w owns O[16*(w&3)..+16, 128*(w>>2)..+128] in registers.
// ---------------------------------------------------------------------------
struct AttnSmem {
    float Qs[64][260];   // [q][d]  tf32 (stride%32==4 -> frag LDS conflict-free)
    float Ks[64][68];    // [k][d-chunk64]
    float Ps[64][68];    // [q][k]  S then P (tf32)
    float Vs[64][264];   // [k][d]  (stride%32==8)
    float m_s[64], l_s[64], sc_s[64];
};

__global__ __launch_bounds__(256, 1) void attn_kernel() {
    extern __shared__ char smem_raw[];
    AttnSmem& S = *reinterpret_cast<AttnSmem*>(smem_raw);

    const int tid  = threadIdx.x;
    const int w    = tid >> 5;
    const int lane = tid & 31;
    const int g    = lane >> 2;   // group id (row within fragment)
    const int t    = lane & 3;    // thread-in-group (col within fragment)
    const int rt   = w & 3;       // row tile (16 rows)
    const int half = w >> 2;      // 0/1: S k-half, PV d-half
    const int rt16 = rt * 16;
    const int qbase = blockIdx.x * 64;
    const int b     = blockIdx.y;
    const float* qkv = g_qkv + (size_t)b * N_TOK * F3;

    // ---- load Q tile (tf32) ----
    {
        int row = tid >> 2, q4 = tid & 3;          // 4 threads/row
#pragma unroll
        for (int i = 0; i < 16; i++) {
            int col = q4 * 64 + i * 4;
            float4 v = *(const float4*)(qkv + (size_t)(qbase + row) * F3 + col);
            S.Qs[row][col + 0] = to_tf32f(v.x); S.Qs[row][col + 1] = to_tf32f(v.y);
            S.Qs[row][col + 2] = to_tf32f(v.z); S.Qs[row][col + 3] = to_tf32f(v.w);
        }
    }
    if (tid < 64) { S.m_s[tid] = -INFINITY; S.l_s[tid] = 0.f; }

    float cO[16][4];
#pragma unroll
    for (int i = 0; i < 16; i++)
#pragma unroll
        for (int j = 0; j < 4; j++) cO[i][j] = 0.f;

    for (int kb = 0; kb < N_TOK; kb += 64) {
        __syncthreads();   // prev PV done: Vs/Ps/Ks free; Q ready on first iter

        // ---- load V tile 64x256 (tf32) ----
        {
            int row = tid >> 2, q4 = tid & 3;
#pragma unroll
            for (int i = 0; i < 16; i++) {
                int col = q4 * 64 + i * 4;
                float4 v = *(const float4*)(qkv + (size_t)(kb + row) * F3 + 512 + col);
                S.Vs[row][col + 0] = to_tf32f(v.x); S.Vs[row][col + 1] = to_tf32f(v.y);
                S.Vs[row][col + 2] = to_tf32f(v.z); S.Vs[row][col + 3] = to_tf32f(v.w);
            }
        }

        // ---- S = Q K^T : d in chunks of 64 ----
        float cS[4][4];
#pragma unroll
        for (int n = 0; n < 4; n++)
#pragma unroll
            for (int j = 0; j < 4; j++) cS[n][j] = 0.f;

        for (int dc = 0; dc < 4; dc++) {
            if (dc > 0) __syncthreads();   // Ks reuse
            {
                int row = tid >> 2, q4 = tid & 3;
#pragma unroll
                for (int i = 0; i < 4; i++) {
                    int col = q4 * 16 + i * 4;
                    float4 v = *(const float4*)(qkv + (size_t)(kb + row) * F3 + 256 + dc * 64 + col);
                    S.Ks[row][col + 0] = to_tf32f(v.x); S.Ks[row][col + 1] = to_tf32f(v.y);
                    S.Ks[row][col + 2] = to_tf32f(v.z); S.Ks[row][col + 3] = to_tf32f(v.w);
                }
            }
            __syncthreads();
#pragma unroll
            for (int kk = 0; kk < 8; kk++) {
                int dq = dc * 64 + kk * 8;     // Qs col
                int dk = kk * 8;               // Ks col
                uint32_t a0 = f2u(S.Qs[rt16 + g    ][dq + t]);
                uint32_t a1 = f2u(S.Qs[rt16 + g + 8][dq + t]);
                uint32_t a2 = f2u(S.Qs[rt16 + g    ][dq + t + 4]);
                uint32_t a3 = f2u(S.Qs[rt16 + g + 8][dq + t + 4]);
#pragma unroll
                for (int nt = 0; nt < 4; nt++) {
                    int kcol = half * 32 + nt * 8 + g;
                    uint32_t b0 = f2u(S.Ks[kcol][dk + t]);
                    uint32_t b1 = f2u(S.Ks[kcol][dk + t + 4]);
                    mma_tf32(cS[nt], a0, a1, a2, a3, b0, b1);
                }
            }
        }

        // ---- store S fragments ----
#pragma unroll
        for (int nt = 0; nt < 4; nt++) {
            int col = half * 32 + nt * 8 + 2 * t;
            S.Ps[rt16 + g    ][col]     = cS[nt][0];
            S.Ps[rt16 + g    ][col + 1] = cS[nt][1];
            S.Ps[rt16 + g + 8][col]     = cS[nt][2];
            S.Ps[rt16 + g + 8][col + 1] = cS[nt][3];
        }
        __syncthreads();

        // ---- online softmax (4 threads/row; cols c = t mod 4 -> conflict-free) ----
        {
            int row = tid >> 2;
            float mx = -INFINITY;
            float vals[16];
#pragma unroll
            for (int i = 0; i < 16; i++) {
                vals[i] = S.Ps[row][t + 4 * i] * SCL;
                mx = fmaxf(mx, vals[i]);
            }
            mx = fmaxf(mx, __shfl_xor_sync(0xffffffffu, mx, 1));
            mx = fmaxf(mx, __shfl_xor_sync(0xffffffffu, mx, 2));
            float mold = S.m_s[row];
            float mnew = fmaxf(mold, mx);
            float sc   = __expf(mold - mnew);   // 0 on first tile
            float sum  = 0.f;
#pragma unroll
            for (int i = 0; i < 16; i++) {
                float e = __expf(vals[i] - mnew);
                sum += e;
                S.Ps[row][t + 4 * i] = to_tf32f(e);
            }
            sum += __shfl_xor_sync(0xffffffffu, sum, 1);
            sum += __shfl_xor_sync(0xffffffffu, sum, 2);
            if (t == 0) {
                S.l_s[row]  = S.l_s[row] * sc + sum;
                S.m_s[row]  = mnew;
                S.sc_s[row] = sc;
            }
        }
        __syncthreads();

        // ---- PV: rescale O, then O += P V ----
        {
            float sct = S.sc_s[rt16 + g];
            float scb = S.sc_s[rt16 + g + 8];
#pragma unroll
            for (int nt = 0; nt < 16; nt++) {
                cO[nt][0] *= sct; cO[nt][1] *= sct;
                cO[nt][2] *= scb; cO[nt][3] *= scb;
            }
        }
#pragma unroll
        for (int kk = 0; kk < 8; kk++) {
            int k0 = kk * 8;
            uint32_t a0 = f2u(S.Ps[rt16 + g    ][k0 + t]);
            uint32_t a1 = f2u(S.Ps[rt16 + g + 8][k0 + t]);
            uint32_t a2 = f2u(S.Ps[rt16 + g    ][k0 + t + 4]);
            uint32_t a3 = f2u(S.Ps[rt16 + g + 8][k0 + t + 4]);
#pragma unroll
            for (int nt = 0; nt < 16; nt++) {
                int dcol = half * 128 + nt * 8 + g;
                uint32_t b0 = f2u(S.Vs[k0 + t    ][dcol]);
                uint32_t b1 = f2u(S.Vs[k0 + t + 4][dcol]);
                mma_tf32(cO[nt], a0, a1, a2, a3, b0, b1);
            }
        }
    }

    // ---- normalize + write ----
    {
        float invt = 1.f / S.l_s[rt16 + g];
        float invb = 1.f / S.l_s[rt16 + g + 8];
        size_t bN = (size_t)b * N_TOK;
        int rowt = qbase + rt16 + g;
        int rowb = rowt + 8;
#pragma unroll
        for (int nt = 0; nt < 16; nt++) {
            int col = half * 128 + nt * 8 + 2 * t;
            float2 vt = make_float2(cO[nt][0] * invt, cO[nt][1] * invt);
            float2 vb = make_float2(cO[nt][2] * invb, cO[nt][3] * invb);
            *(float2*)(&g_obuf[(bN + rowt) * EDIM + col]) = vt;
            *(float2*)(&g_obuf[(bN + rowb) * EDIM + col]) = vb;
        }
    }
}

// ---------------------------------------------------------------------------
// Kernel 3: out[b, e, m] = x + out_w @ o + out_b  (SIMT fp32)
// ---------------------------------------------------------------------------
__global__ void out_kernel(const float* __restrict__ x,
                           const float* __restrict__ w,
                           const float* __restrict__ bias,
                           float* __restrict__ out) {
    __shared__ float Ws[64][17];
    __shared__ float Os[64][17];
    const int tid = threadIdx.x;
    const int tx = tid & 15, ty = tid >> 4;
    const int mbase = blockIdx.x * 64;
    const int ebase = blockIdx.y * 64;
    const int b = blockIdx.z;

    float acc[4][4];
#pragma unroll
    for (int r = 0; r < 4; r++)
#pragma unroll
        for (int c = 0; c < 4; c++) acc[r][c] = 0.f;

    const int ldrow = tid >> 2, ldc4 = tid & 3;
    for (int k0 = 0; k0 < EDIM; k0 += 16) {
        __syncthreads();
        {
            float4 v = *(const float4*)(w + (size_t)(ebase + ldrow) * EDIM + k0 + ldc4 * 4);
            Ws[ldrow][ldc4 * 4 + 0] = v.x; Ws[ldrow][ldc4 * 4 + 1] = v.y;
            Ws[ldrow][ldc4 * 4 + 2] = v.z; Ws[ldrow][ldc4 * 4 + 3] = v.w;
            float4 u = *(const float4*)(g_obuf + ((size_t)b * N_TOK + mbase + ldrow) * EDIM + k0 + ldc4 * 4);
            Os[ldrow][ldc4 * 4 + 0] = u.x; Os[ldrow][ldc4 * 4 + 1] = u.y;
            Os[ldrow][ldc4 * 4 + 2] = u.z; Os[ldrow][ldc4 * 4 + 3] = u.w;
        }
        __syncthreads();
#pragma unroll
        for (int k = 0; k < 16; k++) {
            float wr[4], orr[4];
#pragma unroll
            for (int r = 0; r < 4; r++) wr[r] = Ws[ty * 4 + r][k];
#pragma unroll
            for (int c = 0; c < 4; c++) orr[c] = Os[tx + 16 * c][k];
#pragma unroll
            for (int r = 0; r < 4; r++)
#pragma unroll
                for (int c = 0; c < 4; c++) acc[r][c] += wr[r] * orr[c];
        }
    }

#pragma unroll
    for (int r = 0; r < 4; r++) {
        int e = ebase + ty * 4 + r;
        float bb = bias[e];
#pragma unroll
        for (int c = 0; c < 4; c++) {
            int m = mbase + tx + 16 * c;
            size_t idx = ((size_t)b * EDIM + e) * N_TOK + m;
            out[idx] = x[idx] + acc[r][c] + bb;
        }
    }
}

// ---------------------------------------------------------------------------
extern "C" void kernel_launch(void* const* d_in, const int* in_sizes, int n_in,
                              void* d_out, int out_size) {
    const float* x = nullptr; const float* qkv_w = nullptr; const float* qkv_b = nullptr;
    const float* out_w = nullptr; const float* out_b = nullptr;
    for (int i = 0; i < n_in; i++) {
        switch (in_sizes[i]) {
            case 4194304: x     = (const float*)d_in[i]; break;
            case  196608: qkv_w = (const float*)d_in[i]; break;
            case     768: qkv_b = (const float*)d_in[i]; break;
            case   65536: out_w = (const float*)d_in[i]; break;
            case     256: out_b = (const float*)d_in[i]; break;
            default: break;
        }
    }
    float* out = (float*)d_out;

    cudaFuncSetAttribute(attn_kernel, cudaFuncAttributeMaxDynamicSharedMemorySize,
                         (int)sizeof(AttnSmem));

    qkv_kernel<<<dim3(N_TOK / 64, F3 / 64, B_SZ), 256>>>(x, qkv_w, qkv_b);
    attn_kernel<<<dim3(N_TOK / 64, B_SZ), 256, sizeof(AttnSmem)>>>();
    out_kernel<<<dim3(N_TOK / 64, EDIM / 64, B_SZ), 256>>>(x, out_w, out_b, out);
}

// round 5
// speedup vs baseline: 3.3416x; 1.7470x over previous
#include <cuda_runtime.h>
#include <cuda_bf16.h>
#include <math.h>
#include <stdint.h>

#define B_SZ   4
#define EDIM   256
#define N_TOK  4096
#define F3     768
#define SCL    0.0625f   // 1/sqrt(256)

// Scratch (allocation-free rule: __device__ globals)
__device__ __nv_bfloat16 g_qkvh[(size_t)B_SZ * N_TOK * F3]; // [b, n, 3E] bf16
__device__ float g_obuf[(size_t)B_SZ * N_TOK * EDIM];       // [b, n, E] fp32

__device__ __forceinline__ void ldsm_x4(uint32_t& r0, uint32_t& r1, uint32_t& r2, uint32_t& r3,
                                        uint32_t addr) {
    asm volatile("ldmatrix.sync.aligned.m8n8.x4.shared.b16 {%0,%1,%2,%3}, [%4];"
                 : "=r"(r0), "=r"(r1), "=r"(r2), "=r"(r3) : "r"(addr));
}
__device__ __forceinline__ void ldsm_x4_t(uint32_t& r0, uint32_t& r1, uint32_t& r2, uint32_t& r3,
                                          uint32_t addr) {
    asm volatile("ldmatrix.sync.aligned.m8n8.x4.trans.shared.b16 {%0,%1,%2,%3}, [%4];"
                 : "=r"(r0), "=r"(r1), "=r"(r2), "=r"(r3) : "r"(addr));
}
__device__ __forceinline__ void mma_bf16(float c[4], uint32_t a0, uint32_t a1, uint32_t a2,
                                         uint32_t a3, uint32_t b0, uint32_t b1) {
    asm volatile(
        "mma.sync.aligned.m16n8k16.row.col.f32.bf16.bf16.f32 "
        "{%0,%1,%2,%3}, {%4,%5,%6,%7}, {%8,%9}, {%0,%1,%2,%3};\n"
        : "+f"(c[0]), "+f"(c[1]), "+f"(c[2]), "+f"(c[3])
        : "r"(a0), "r"(a1), "r"(a2), "r"(a3), "r"(b0), "r"(b1));
}
__device__ __forceinline__ uint32_t sptr(const void* p) {
    return (uint32_t)__cvta_generic_to_shared(p);
}

// ---------------------------------------------------------------------------
// Kernel 1: qkv[b, m, f] = sum_e x[b, e, m] * w[f, e] + bias[f]
// fp32 SIMT accumulate, bf16 output.
// ---------------------------------------------------------------------------
__global__ void qkv_kernel(const float* __restrict__ x,
                           const float* __restrict__ w,
                           const float* __restrict__ bias) {
    __shared__ float Xs[16][64];
    __shared__ float Ws[64][17];
    const int tid = threadIdx.x;
    const int tx = tid & 15, ty = tid >> 4;
    const int mbase = blockIdx.x * 64;
    const int fbase = blockIdx.y * 64;
    const int b = blockIdx.z;
    const float* xb = x + (size_t)b * EDIM * N_TOK;

    float acc[4][4];
#pragma unroll
    for (int r = 0; r < 4; r++)
#pragma unroll
        for (int c = 0; c < 4; c++) acc[r][c] = 0.f;

    for (int e0 = 0; e0 < EDIM; e0 += 16) {
        __syncthreads();
        {
            int e = tid >> 4, m4 = tid & 15;
            float4 v = *(const float4*)(xb + (size_t)(e0 + e) * N_TOK + mbase + m4 * 4);
            *(float4*)(&Xs[e][m4 * 4]) = v;
        }
        {
            int f = tid >> 2, e4 = tid & 3;
            float4 v = *(const float4*)(w + (size_t)(fbase + f) * EDIM + e0 + e4 * 4);
            Ws[f][e4 * 4 + 0] = v.x; Ws[f][e4 * 4 + 1] = v.y;
            Ws[f][e4 * 4 + 2] = v.z; Ws[f][e4 * 4 + 3] = v.w;
        }
        __syncthreads();
#pragma unroll
        for (int e = 0; e < 16; e++) {
            float xr[4], wr[4];
#pragma unroll
            for (int r = 0; r < 4; r++) xr[r] = Xs[e][ty * 4 + r];
#pragma unroll
            for (int c = 0; c < 4; c++) wr[c] = Ws[tx + 16 * c][e];
#pragma unroll
            for (int r = 0; r < 4; r++)
#pragma unroll
                for (int c = 0; c < 4; c++) acc[r][c] += xr[r] * wr[c];
        }
    }

#pragma unroll
    for (int c = 0; c < 4; c++) {
        int f = fbase + tx + 16 * c;
        float bb = bias[f];
#pragma unroll
        for (int r = 0; r < 4; r++) {
            size_t m = (size_t)mbase + ty * 4 + r;
            g_qkvh[((size_t)b * N_TOK + m) * F3 + f] = __float2bfloat16(acc[r][c] + bb);
        }
    }
}

// ---------------------------------------------------------------------------
// Kernel 2: flash attention, bf16 mma m16n8k16 + ldmatrix.
// CTA: 64 q rows, 8 warps. warp w: rt=w&3 (16 q rows), half=w>>2.
//   S : warp tile 16 x 32 (k-half), d-depth 256 in 4 chunks of 64.
//   PV: warp tile 16 x 128 (d-half), k-depth 64.
// All smem tile row strides are ≡16 bytes (mod 128) -> conflict-free ldmatrix.
// ---------------------------------------------------------------------------
#define QS_STRIDE 264   // bf16: 528B row, 528%128==16
#define VS_STRIDE 264
#define KS_STRIDE 72    // 144B row, 144%128==16
#define PS_STRIDE 72
#define SS_STRIDE 68    // fp32

struct AttnSmem {
    __nv_bfloat16 Qs[64][QS_STRIDE];
    __nv_bfloat16 Vs[64][VS_STRIDE];
    __nv_bfloat16 Ks[64][KS_STRIDE];
    __nv_bfloat16 Ps[64][PS_STRIDE];
    float Ss[64][SS_STRIDE];
    float m_s[64], l_s[64], sc_s[64];
};

__global__ __launch_bounds__(256, 2) void attn_kernel() {
    extern __shared__ char smem_raw[];
    AttnSmem& S = *reinterpret_cast<AttnSmem*>(smem_raw);

    const int tid  = threadIdx.x;
    const int lane = tid & 31;
    const int w    = tid >> 5;
    const int g    = lane >> 2;
    const int t    = lane & 3;
    const int rt16 = (w & 3) * 16;
    const int half = w >> 2;
    const int qbase = blockIdx.x * 64;
    const int b     = blockIdx.y;
    const __nv_bfloat16* qkv = g_qkvh + (size_t)b * N_TOK * F3;

    const int ldrow = tid >> 2, ldq4 = tid & 3;   // 4 threads per tile row

    // ---- load Q tile [64][256] bf16 ----
#pragma unroll
    for (int i = 0; i < 8; i++) {
        int col = ldq4 * 64 + i * 8;
        uint4 v = *(const uint4*)(qkv + (size_t)(qbase + ldrow) * F3 + col);
        *(uint4*)(&S.Qs[ldrow][col]) = v;
    }
    if (tid < 64) { S.m_s[tid] = -INFINITY; S.l_s[tid] = 0.f; }

    float cO[16][4];
#pragma unroll
    for (int i = 0; i < 16; i++)
#pragma unroll
        for (int j = 0; j < 4; j++) cO[i][j] = 0.f;

    // ldmatrix lane-address components (constant over loop)
    const int a_row = rt16 + (lane & 15);           // A frags (Q and P): rows
    const int a_coff = (lane >> 4) * 8;             // A k-offset
    const int bk_row = half * 32 + ((lane >> 4) & 1) * 8 + (lane & 7); // K tile n-row
    const int bk_coff = ((lane >> 3) & 1) * 8;                          // K k-offset
    const int bv_krow = ((lane >> 3) & 1) * 8 + (lane & 7);             // V k-row offset
    const int bv_doff = (lane >> 4) * 8;                                // V d-offset

    for (int kb = 0; kb < N_TOK; kb += 64) {
        __syncthreads();   // Vs/Ps free (prev PV done)

        // ---- load V tile [64][256] bf16 ----
#pragma unroll
        for (int i = 0; i < 8; i++) {
            int col = ldq4 * 64 + i * 8;
            uint4 v = *(const uint4*)(qkv + (size_t)(kb + ldrow) * F3 + 512 + col);
            *(uint4*)(&S.Vs[ldrow][col]) = v;
        }

        // ---- S = Q K^T over d in 4 chunks of 64 ----
        float cS[4][4];
#pragma unroll
        for (int n = 0; n < 4; n++)
#pragma unroll
            for (int j = 0; j < 4; j++) cS[n][j] = 0.f;

        for (int dc = 0; dc < 4; dc++) {
            if (dc > 0) __syncthreads();
            {   // Ks chunk [64 tok][64 d]
#pragma unroll
                for (int i = 0; i < 2; i++) {
                    int col = ldq4 * 16 + i * 8;
                    uint4 v = *(const uint4*)(qkv + (size_t)(kb + ldrow) * F3 + 256 + dc * 64 + col);
                    *(uint4*)(&S.Ks[ldrow][col]) = v;
                }
            }
            __syncthreads();
#pragma unroll
            for (int ks = 0; ks < 4; ks++) {
                uint32_t a0, a1, a2, a3;
                ldsm_x4(a0, a1, a2, a3, sptr(&S.Qs[a_row][dc * 64 + ks * 16 + a_coff]));
#pragma unroll
                for (int p = 0; p < 2; p++) {
                    uint32_t b0, b1, b2, b3;
                    ldsm_x4(b0, b1, b2, b3,
                            sptr(&S.Ks[bk_row + p * 16][ks * 16 + bk_coff]));
                    mma_bf16(cS[2 * p],     a0, a1, a2, a3, b0, b1);
                    mma_bf16(cS[2 * p + 1], a0, a1, a2, a3, b2, b3);
                }
            }
        }

        // ---- store S fragments (fp32) ----
#pragma unroll
        for (int nt = 0; nt < 4; nt++) {
            int col = half * 32 + nt * 8 + 2 * t;
            *(float2*)(&S.Ss[rt16 + g][col])     = make_float2(cS[nt][0], cS[nt][1]);
            *(float2*)(&S.Ss[rt16 + g + 8][col]) = make_float2(cS[nt][2], cS[nt][3]);
        }
        __syncthreads();

        // ---- online softmax (4 threads/row) ----
        {
            int row = tid >> 2;
            float vals[16];
            float mx = -INFINITY;
#pragma unroll
            for (int i = 0; i < 16; i++) {
                vals[i] = S.Ss[row][t + 4 * i] * SCL;
                mx = fmaxf(mx, vals[i]);
            }
            mx = fmaxf(mx, __shfl_xor_sync(0xffffffffu, mx, 1));
            mx = fmaxf(mx, __shfl_xor_sync(0xffffffffu, mx, 2));
            float mold = S.m_s[row];
            float mnew = fmaxf(mold, mx);
            float sc   = __expf(mold - mnew);
            float sum  = 0.f;
#pragma unroll
            for (int i = 0; i < 16; i++) {
                float e = __expf(vals[i] - mnew);
                sum += e;
                S.Ps[row][t + 4 * i] = __float2bfloat16(e);
            }
            sum += __shfl_xor_sync(0xffffffffu, sum, 1);
            sum += __shfl_xor_sync(0xffffffffu, sum, 2);
            if (t == 0) {
                S.l_s[row]  = S.l_s[row] * sc + sum;
                S.m_s[row]  = mnew;
                S.sc_s[row] = sc;
            }
        }
        __syncthreads();

        // ---- PV: rescale O, then O += P V (k-depth 64 = 4 ksteps) ----
        {
            float sct = S.sc_s[rt16 + g];
            float scb = S.sc_s[rt16 + g + 8];
#pragma unroll
            for (int nt = 0; nt < 16; nt++) {
                cO[nt][0] *= sct; cO[nt][1] *= sct;
                cO[nt][2] *= scb; cO[nt][3] *= scb;
            }
        }
#pragma unroll
        for (int ks = 0; ks < 4; ks++) {
            uint32_t a0, a1, a2, a3;
            ldsm_x4(a0, a1, a2, a3, sptr(&S.Ps[a_row][ks * 16 + a_coff]));
#pragma unroll
            for (int p = 0; p < 8; p++) {
                uint32_t b0, b1, b2, b3;
                ldsm_x4_t(b0, b1, b2, b3,
                          sptr(&S.Vs[ks * 16 + bv_krow][half * 128 + p * 16 + bv_doff]));
                mma_bf16(cO[2 * p],     a0, a1, a2, a3, b0, b1);
                mma_bf16(cO[2 * p + 1], a0, a1, a2, a3, b2, b3);
            }
        }
    }

    // ---- normalize + write (fp32) ----
    {
        float invt = 1.f / S.l_s[rt16 + g];
        float invb = 1.f / S.l_s[rt16 + g + 8];
        size_t bN = (size_t)b * N_TOK;
        int rowt = qbase + rt16 + g;
        int rowb = rowt + 8;
#pragma unroll
        for (int nt = 0; nt < 16; nt++) {
            int col = half * 128 + nt * 8 + 2 * t;
            *(float2*)(&g_obuf[(bN + rowt) * EDIM + col]) =
                make_float2(cO[nt][0] * invt, cO[nt][1] * invt);
            *(float2*)(&g_obuf[(bN + rowb) * EDIM + col]) =
                make_float2(cO[nt][2] * invb, cO[nt][3] * invb);
        }
    }
}

// ---------------------------------------------------------------------------
// Kernel 3: out[b, e, m] = x + out_w @ o + out_b  (SIMT fp32)
// ---------------------------------------------------------------------------
__global__ void out_kernel(const float* __restrict__ x,
                           const float* __restrict__ w,
                           const float* __restrict__ bias,
                           float* __restrict__ out) {
    __shared__ float Ws[64][17];
    __shared__ float Os[64][17];
    const int tid = threadIdx.x;
    const int tx = tid & 15, ty = tid >> 4;
    const int mbase = blockIdx.x * 64;
    const int ebase = blockIdx.y * 64;
    const int b = blockIdx.z;

    float acc[4][4];
#pragma unroll
    for (int r = 0; r < 4; r++)
#pragma unroll
        for (int c = 0; c < 4; c++) acc[r][c] = 0.f;

    const int ldrow = tid >> 2, ldc4 = tid & 3;
    for (int k0 = 0; k0 < EDIM; k0 += 16) {
        __syncthreads();
        {
            float4 v = *(const float4*)(w + (size_t)(ebase + ldrow) * EDIM + k0 + ldc4 * 4);
            Ws[ldrow][ldc4 * 4 + 0] = v.x; Ws[ldrow][ldc4 * 4 + 1] = v.y;
            Ws[ldrow][ldc4 * 4 + 2] = v.z; Ws[ldrow][ldc4 * 4 + 3] = v.w;
            float4 u = *(const float4*)(g_obuf + ((size_t)b * N_TOK + mbase + ldrow) * EDIM + k0 + ldc4 * 4);
            Os[ldrow][ldc4 * 4 + 0] = u.x; Os[ldrow][ldc4 * 4 + 1] = u.y;
            Os[ldrow][ldc4 * 4 + 2] = u.z; Os[ldrow][ldc4 * 4 + 3] = u.w;
        }
        __syncthreads();
#pragma unroll
        for (int k = 0; k < 16; k++) {
            float wr[4], orr[4];
#pragma unroll
            for (int r = 0; r < 4; r++) wr[r] = Ws[ty * 4 + r][k];
#pragma unroll
            for (int c = 0; c < 4; c++) orr[c] = Os[tx + 16 * c][k];
#pragma unroll
            for (int r = 0; r < 4; r++)
#pragma unroll
                for (int c = 0; c < 4; c++) acc[r][c] += wr[r] * orr[c];
        }
    }

#pragma unroll
    for (int r = 0; r < 4; r++) {
        int e = ebase + ty * 4 + r;
        float bb = bias[e];
#pragma unroll
        for (int c = 0; c < 4; c++) {
            int m = mbase + tx + 16 * c;
            size_t idx = ((size_t)b * EDIM + e) * N_TOK + m;
            out[idx] = x[idx] + acc[r][c] + bb;
        }
    }
}

// ---------------------------------------------------------------------------
extern "C" void kernel_launch(void* const* d_in, const int* in_sizes, int n_in,
                              void* d_out, int out_size) {
    const float* x = nullptr; const float* qkv_w = nullptr; const float* qkv_b = nullptr;
    const float* out_w = nullptr; const float* out_b = nullptr;
    for (int i = 0; i < n_in; i++) {
        switch (in_sizes[i]) {
            case 4194304: x     = (const float*)d_in[i]; break;
            case  196608: qkv_w = (const float*)d_in[i]; break;
            case     768: qkv_b = (const float*)d_in[i]; break;
            case   65536: out_w = (const float*)d_in[i]; break;
            case     256: out_b = (const float*)d_in[i]; break;
            default: break;
        }
    }
    float* out = (float*)d_out;

    cudaFuncSetAttribute(attn_kernel, cudaFuncAttributeMaxDynamicSharedMemorySize,
                         (int)sizeof(AttnSmem));

    qkv_kernel<<<dim3(N_TOK / 64, F3 / 64, B_SZ), 256>>>(x, qkv_w, qkv_b);
    attn_kernel<<<dim3(N_TOK / 64, B_SZ), 256, sizeof(AttnSmem)>>>();
    out_kernel<<<dim3(N_TOK / 64, EDIM / 64, B_SZ), 256>>>(x, out_w, out_b, out);
}

// round 7
// speedup vs baseline: 4.2933x; 1.2848x over previous
#include <cuda_runtime.h>
#include <cuda_bf16.h>
#include <math.h>
#include <stdint.h>

#define B_SZ   4
#define EDIM   256
#define N_TOK  4096
#define F3     768
#define SCL    0.0625f   // 1/sqrt(256)

// Scratch (allocation-free rule: __device__ globals)
__device__ __align__(16) __nv_bfloat16 g_qkvh[(size_t)B_SZ * N_TOK * F3]; // [b, n, 3E]
__device__ __align__(16) __nv_bfloat16 g_obh[(size_t)B_SZ * N_TOK * EDIM]; // [b, n, E]

__device__ __forceinline__ void ldsm_x4(uint32_t& r0, uint32_t& r1, uint32_t& r2, uint32_t& r3,
                                        uint32_t addr) {
    asm volatile("ldmatrix.sync.aligned.m8n8.x4.shared.b16 {%0,%1,%2,%3}, [%4];"
                 : "=r"(r0), "=r"(r1), "=r"(r2), "=r"(r3) : "r"(addr));
}
__device__ __forceinline__ void ldsm_x4_t(uint32_t& r0, uint32_t& r1, uint32_t& r2, uint32_t& r3,
                                          uint32_t addr) {
    asm volatile("ldmatrix.sync.aligned.m8n8.x4.trans.shared.b16 {%0,%1,%2,%3}, [%4];"
                 : "=r"(r0), "=r"(r1), "=r"(r2), "=r"(r3) : "r"(addr));
}
__device__ __forceinline__ void mma_bf16(float c[4], uint32_t a0, uint32_t a1, uint32_t a2,
                                         uint32_t a3, uint32_t b0, uint32_t b1) {
    asm volatile(
        "mma.sync.aligned.m16n8k16.row.col.f32.bf16.bf16.f32 "
        "{%0,%1,%2,%3}, {%4,%5,%6,%7}, {%8,%9}, {%0,%1,%2,%3};\n"
        : "+f"(c[0]), "+f"(c[1]), "+f"(c[2]), "+f"(c[3])
        : "r"(a0), "r"(a1), "r"(a2), "r"(a3), "r"(b0), "r"(b1));
}
__device__ __forceinline__ uint32_t sptr(const void* p) {
    return (uint32_t)__cvta_generic_to_shared(p);
}
// pack (lo, hi) floats into bf16x2 (lo in low half). cvt d,a,b: a->high, b->low
__device__ __forceinline__ uint32_t bf2pack(float lo, float hi) {
    uint32_t r;
    asm("cvt.rn.bf16x2.f32 %0, %1, %2;" : "=r"(r) : "f"(hi), "f"(lo));
    return r;
}

// ---------------------------------------------------------------------------
// Kernel 1: qkv[b, m, f] = sum_e x[b, e, m] * w[f, e] + bias[f]   (bf16 mma)
// CTA: 128 m x 64 f. Warps 4(m) x 2(f), warp tile 32m x 32f.
// A from Xs[e][m] via ldmatrix.trans; B from Ws[f][e] via ldmatrix.
// ---------------------------------------------------------------------------
#define XS_STRIDE 136   // 272B % 128 == 16 -> conflict-free ldsm
#define WS_STRIDE 72    // 144B % 128 == 16

__global__ __launch_bounds__(256) void qkv_kernel(const float* __restrict__ x,
                                                  const float* __restrict__ w,
                                                  const float* __restrict__ bias) {
    __shared__ __nv_bfloat16 Xs[64][XS_STRIDE];   // [e][m]
    __shared__ __nv_bfloat16 Ws[64][WS_STRIDE];   // [f][e]
    const int tid  = threadIdx.x;
    const int lane = tid & 31;
    const int wp   = tid >> 5;
    const int g    = lane >> 2;
    const int t    = lane & 3;
    const int wm   = wp >> 1;           // 0..3 : m-subtile of 32
    const int wf   = wp & 1;            // 0..1 : f-subtile of 32
    const int mbase = blockIdx.x * 128;
    const int fbase = blockIdx.y * 64;
    const int b     = blockIdx.z;
    const float* xb = x + (size_t)b * EDIM * N_TOK;

    float c[2][4][4];
#pragma unroll
    for (int i = 0; i < 2; i++)
#pragma unroll
        for (int j = 0; j < 4; j++)
#pragma unroll
            for (int q = 0; q < 4; q++) c[i][j][q] = 0.f;

    // ldsm address components
    const int at_row = (lane >> 4) * 8 + (lane & 7);        // A-trans: e-offset
    const int at_col = ((lane >> 3) & 1) * 8;               // A-trans: m-offset
    const int bk_row = wf * 32 + ((lane >> 4) & 1) * 8 + (lane & 7);  // B: f-row
    const int bk_col = ((lane >> 3) & 1) * 8;               // B: e-offset

    for (int e0 = 0; e0 < EDIM; e0 += 64) {
        __syncthreads();
        // Xs[e][m]: gmem read coalesced along m, bf16 convert
#pragma unroll
        for (int i = 0; i < 8; i++) {
            int lin = tid + i * 256;               // 64 e x 32 m4
            int e = lin >> 5, m4 = (lin & 31) * 4;
            float4 v = *(const float4*)(xb + (size_t)(e0 + e) * N_TOK + mbase + m4);
            uint32_t p0 = bf2pack(v.x, v.y), p1 = bf2pack(v.z, v.w);
            *(uint2*)(&Xs[e][m4]) = make_uint2(p0, p1);
        }
        // Ws[f][e]
#pragma unroll
        for (int i = 0; i < 4; i++) {
            int lin = tid + i * 256;               // 64 f x 16 e4
            int f = lin >> 4, e4 = (lin & 15) * 4;
            float4 v = *(const float4*)(w + (size_t)(fbase + f) * EDIM + e0 + e4);
            uint32_t p0 = bf2pack(v.x, v.y), p1 = bf2pack(v.z, v.w);
            *(uint2*)(&Ws[f][e4]) = make_uint2(p0, p1);
        }
        __syncthreads();

#pragma unroll
        for (int ks = 0; ks < 4; ks++) {
            uint32_t a[2][4];
#pragma unroll
            for (int mi = 0; mi < 2; mi++)
                ldsm_x4_t(a[mi][0], a[mi][1], a[mi][2], a[mi][3],
                          sptr(&Xs[ks * 16 + at_row][wm * 32 + mi * 16 + at_col]));
#pragma unroll
            for (int p = 0; p < 2; p++) {
                uint32_t b0, b1, b2, b3;
                ldsm_x4(b0, b1, b2, b3, sptr(&Ws[bk_row + p * 16][ks * 16 + bk_col]));
#pragma unroll
                for (int mi = 0; mi < 2; mi++) {
                    mma_bf16(c[mi][2 * p],     a[mi][0], a[mi][1], a[mi][2], a[mi][3], b0, b1);
                    mma_bf16(c[mi][2 * p + 1], a[mi][0], a[mi][1], a[mi][2], a[mi][3], b2, b3);
                }
            }
        }
    }

    // epilogue: + bias, bf16 pack, store [m][f]
#pragma unroll
    for (int ni = 0; ni < 4; ni++) {
        int f = fbase + wf * 32 + ni * 8 + 2 * t;
        float2 bb = *(const float2*)(bias + f);
#pragma unroll
        for (int mi = 0; mi < 2; mi++) {
            int m0 = mbase + wm * 32 + mi * 16 + g;
            uint32_t ptop = bf2pack(c[mi][ni][0] + bb.x, c[mi][ni][1] + bb.y);
            uint32_t pbot = bf2pack(c[mi][ni][2] + bb.x, c[mi][ni][3] + bb.y);
            *(uint32_t*)(&g_qkvh[((size_t)b * N_TOK + m0) * F3 + f])     = ptop;
            *(uint32_t*)(&g_qkvh[((size_t)b * N_TOK + m0 + 8) * F3 + f]) = pbot;
        }
    }
}

// ---------------------------------------------------------------------------
// Kernel 2: flash attention, bf16 mma m16n8k16 + ldmatrix.
// ---------------------------------------------------------------------------
#define QS_STRIDE 264
#define VS_STRIDE 264
#define KS_STRIDE 72
#define PS_STRIDE 72
#define SS_STRIDE 68

struct AttnSmem {
    __nv_bfloat16 Qs[64][QS_STRIDE];
    __nv_bfloat16 Vs[64][VS_STRIDE];
    __nv_bfloat16 Ks[64][KS_STRIDE];
    __nv_bfloat16 Ps[64][PS_STRIDE];
    float Ss[64][SS_STRIDE];
    float m_s[64], l_s[64], sc_s[64];
};

__global__ __launch_bounds__(256, 2) void attn_kernel() {
    extern __shared__ char smem_raw[];
    AttnSmem& S = *reinterpret_cast<AttnSmem*>(smem_raw);

    const int tid  = threadIdx.x;
    const int lane = tid & 31;
    const int w    = tid >> 5;
    const int g    = lane >> 2;
    const int t    = lane & 3;
    const int rt16 = (w & 3) * 16;
    const int half = w >> 2;
    const int qbase = blockIdx.x * 64;
    const int b     = blockIdx.y;
    const __nv_bfloat16* qkv = g_qkvh + (size_t)b * N_TOK * F3;

    const int ldrow = tid >> 2, ldq4 = tid & 3;

#pragma unroll
    for (int i = 0; i < 8; i++) {
        int col = ldq4 * 64 + i * 8;
        uint4 v = *(const uint4*)(qkv + (size_t)(qbase + ldrow) * F3 + col);
        *(uint4*)(&S.Qs[ldrow][col]) = v;
    }
    if (tid < 64) { S.m_s[tid] = -INFINITY; S.l_s[tid] = 0.f; }

    float cO[16][4];
#pragma unroll
    for (int i = 0; i < 16; i++)
#pragma unroll
        for (int j = 0; j < 4; j++) cO[i][j] = 0.f;

    const int a_row  = rt16 + (lane & 15);
    const int a_coff = (lane >> 4) * 8;
    const int bk_row = half * 32 + ((lane >> 4) & 1) * 8 + (lane & 7);
    const int bk_coff = ((lane >> 3) & 1) * 8;
    const int bv_krow = ((lane >> 3) & 1) * 8 + (lane & 7);
    const int bv_doff = (lane >> 4) * 8;

    for (int kb = 0; kb < N_TOK; kb += 64) {
        __syncthreads();

#pragma unroll
        for (int i = 0; i < 8; i++) {
            int col = ldq4 * 64 + i * 8;
            uint4 v = *(const uint4*)(qkv + (size_t)(kb + ldrow) * F3 + 512 + col);
            *(uint4*)(&S.Vs[ldrow][col]) = v;
        }

        float cS[4][4];
#pragma unroll
        for (int n = 0; n < 4; n++)
#pragma unroll
            for (int j = 0; j < 4; j++) cS[n][j] = 0.f;

        for (int dc = 0; dc < 4; dc++) {
            if (dc > 0) __syncthreads();
#pragma unroll
            for (int i = 0; i < 2; i++) {
                int col = ldq4 * 16 + i * 8;
                uint4 v = *(const uint4*)(qkv + (size_t)(kb + ldrow) * F3 + 256 + dc * 64 + col);
                *(uint4*)(&S.Ks[ldrow][col]) = v;
            }
            __syncthreads();
#pragma unroll
            for (int ks = 0; ks < 4; ks++) {
                uint32_t a0, a1, a2, a3;
                ldsm_x4(a0, a1, a2, a3, sptr(&S.Qs[a_row][dc * 64 + ks * 16 + a_coff]));
#pragma unroll
                for (int p = 0; p < 2; p++) {
                    uint32_t b0, b1, b2, b3;
                    ldsm_x4(b0, b1, b2, b3,
                            sptr(&S.Ks[bk_row + p * 16][ks * 16 + bk_coff]));
                    mma_bf16(cS[2 * p],     a0, a1, a2, a3, b0, b1);
                    mma_bf16(cS[2 * p + 1], a0, a1, a2, a3, b2, b3);
                }
            }
        }

#pragma unroll
        for (int nt = 0; nt < 4; nt++) {
            int col = half * 32 + nt * 8 + 2 * t;
            *(float2*)(&S.Ss[rt16 + g][col])     = make_float2(cS[nt][0], cS[nt][1]);
            *(float2*)(&S.Ss[rt16 + g + 8][col]) = make_float2(cS[nt][2], cS[nt][3]);
        }
        __syncthreads();

        {
            int row = tid >> 2;
            float vals[16];
            float mx = -INFINITY;
#pragma unroll
            for (int i = 0; i < 16; i++) {
                vals[i] = S.Ss[row][t + 4 * i] * SCL;
                mx = fmaxf(mx, vals[i]);
            }
            mx = fmaxf(mx, __shfl_xor_sync(0xffffffffu, mx, 1));
            mx = fmaxf(mx, __shfl_xor_sync(0xffffffffu, mx, 2));
            float mold = S.m_s[row];
            float mnew = fmaxf(mold, mx);
            float sc   = __expf(mold - mnew);
            float sum  = 0.f;
#pragma unroll
            for (int i = 0; i < 16; i++) {
                float e = __expf(vals[i] - mnew);
                sum += e;
                S.Ps[row][t + 4 * i] = __float2bfloat16(e);
            }
            sum += __shfl_xor_sync(0xffffffffu, sum, 1);
            sum += __shfl_xor_sync(0xffffffffu, sum, 2);
            if (t == 0) {
                S.l_s[row]  = S.l_s[row] * sc + sum;
                S.m_s[row]  = mnew;
                S.sc_s[row] = sc;
            }
        }
        __syncthreads();

        {
            float sct = S.sc_s[rt16 + g];
            float scb = S.sc_s[rt16 + g + 8];
#pragma unroll
            for (int nt = 0; nt < 16; nt++) {
                cO[nt][0] *= sct; cO[nt][1] *= sct;
                cO[nt][2] *= scb; cO[nt][3] *= scb;
            }
        }
#pragma unroll
        for (int ks = 0; ks < 4; ks++) {
            uint32_t a0, a1, a2, a3;
            ldsm_x4(a0, a1, a2, a3, sptr(&S.Ps[a_row][ks * 16 + a_coff]));
#pragma unroll
            for (int p = 0; p < 8; p++) {
                uint32_t b0, b1, b2, b3;
                ldsm_x4_t(b0, b1, b2, b3,
                          sptr(&S.Vs[ks * 16 + bv_krow][half * 128 + p * 16 + bv_doff]));
                mma_bf16(cO[2 * p],     a0, a1, a2, a3, b0, b1);
                mma_bf16(cO[2 * p + 1], a0, a1, a2, a3, b2, b3);
            }
        }
    }

    // normalize + write bf16
    {
        float invt = 1.f / S.l_s[rt16 + g];
        float invb = 1.f / S.l_s[rt16 + g + 8];
        size_t bN = (size_t)b * N_TOK;
        int rowt = qbase + rt16 + g;
        int rowb = rowt + 8;
#pragma unroll
        for (int nt = 0; nt < 16; nt++) {
            int col = half * 128 + nt * 8 + 2 * t;
            *(uint32_t*)(&g_obh[(bN + rowt) * EDIM + col]) =
                bf2pack(cO[nt][0] * invt, cO[nt][1] * invt);
            *(uint32_t*)(&g_obh[(bN + rowb) * EDIM + col]) =
                bf2pack(cO[nt][2] * invb, cO[nt][3] * invb);
        }
    }
}

// ---------------------------------------------------------------------------
// Kernel 3: out[b, e, m] = x + sum_k out_w[e,k] * o[m,k] + out_b[e]  (bf16 mma)
// CTA: 64 e x 128 m. Warps 2(e) x 4(m), warp tile 32e x 32m.
// ---------------------------------------------------------------------------
__global__ __launch_bounds__(256) void out_kernel(const float* __restrict__ x,
                                                  const float* __restrict__ w,
                                                  const float* __restrict__ bias,
                                                  float* __restrict__ out) {
    __shared__ __nv_bfloat16 Ws2[64][WS_STRIDE];   // [e][k]
    __shared__ __nv_bfloat16 Os[128][WS_STRIDE];   // [m][k]
    const int tid  = threadIdx.x;
    const int lane = tid & 31;
    const int wp   = tid >> 5;
    const int g    = lane >> 2;
    const int t    = lane & 3;
    const int we   = wp & 1;            // e-subtile of 32
    const int wm   = wp >> 1;           // m-subtile of 32
    const int mbase = blockIdx.x * 128;
    const int ebase = blockIdx.y * 64;
    const int b     = blockIdx.z;

    float c[2][4][4];
#pragma unroll
    for (int i = 0; i < 2; i++)
#pragma unroll
        for (int j = 0; j < 4; j++)
#pragma unroll
            for (int q = 0; q < 4; q++) c[i][j][q] = 0.f;

    const int a_row  = we * 32 + (lane & 15);
    const int a_coff = (lane >> 4) * 8;
    const int b_row  = wm * 32 + ((lane >> 4) & 1) * 8 + (lane & 7);
    const int b_coff = ((lane >> 3) & 1) * 8;

    for (int k0 = 0; k0 < EDIM; k0 += 64) {
        __syncthreads();
#pragma unroll
        for (int i = 0; i < 4; i++) {
            int lin = tid + i * 256;               // 64 e x 16 k4
            int e = lin >> 4, k4 = (lin & 15) * 4;
            float4 v = *(const float4*)(w + (size_t)(ebase + e) * EDIM + k0 + k4);
            uint32_t p0 = bf2pack(v.x, v.y), p1 = bf2pack(v.z, v.w);
            *(uint2*)(&Ws2[e][k4]) = make_uint2(p0, p1);
        }
#pragma unroll
        for (int i = 0; i < 4; i++) {
            int lin = tid + i * 256;               // 128 m x 8 k8
            int m = lin >> 3, k8 = (lin & 7) * 8;
            uint4 v = *(const uint4*)(g_obh + ((size_t)b * N_TOK + mbase + m) * EDIM + k0 + k8);
            *(uint4*)(&Os[m][k8]) = v;
        }
        __syncthreads();

#pragma unroll
        for (int ks = 0; ks < 4; ks++) {
            uint32_t a[2][4];
#pragma unroll
            for (int mi = 0; mi < 2; mi++)
                ldsm_x4(a[mi][0], a[mi][1], a[mi][2], a[mi][3],
                        sptr(&Ws2[a_row + mi * 16][ks * 16 + a_coff]));
#pragma unroll
            for (int p = 0; p < 2; p++) {
                uint32_t b0, b1, b2, b3;
                ldsm_x4(b0, b1, b2, b3, sptr(&Os[b_row + p * 16][ks * 16 + b_coff]));
#pragma unroll
                for (int mi = 0; mi < 2; mi++) {
                    mma_bf16(c[mi][2 * p],     a[mi][0], a[mi][1], a[mi][2], a[mi][3], b0, b1);
                    mma_bf16(c[mi][2 * p + 1], a[mi][0], a[mi][1], a[mi][2], a[mi][3], b2, b3);
                }
            }
        }
    }

    // epilogue: residual + bias, fp32 out [e][m]
#pragma unroll
    for (int mi = 0; mi < 2; mi++) {
        int e0 = ebase + we * 32 + mi * 16 + g;
        float bt = bias[e0], bb = bias[e0 + 8];
#pragma unroll
        for (int ni = 0; ni < 4; ni++) {
            int m = mbase + wm * 32 + ni * 8 + 2 * t;
            size_t it = ((size_t)b * EDIM + e0) * N_TOK + m;
            size_t ib = ((size_t)b * EDIM + e0 + 8) * N_TOK + m;
            float2 xt = *(const float2*)(x + it);
            float2 xb = *(const float2*)(x + ib);
            *(float2*)(out + it) = make_float2(xt.x + c[mi][ni][0] + bt,
                                               xt.y + c[mi][ni][1] + bt);
            *(float2*)(out + ib) = make_float2(xb.x + c[mi][ni][2] + bb,
                                               xb.y + c[mi][ni][3] + bb);
        }
    }
}

// ---------------------------------------------------------------------------
extern "C" void kernel_launch(void* const* d_in, const int* in_sizes, int n_in,
                              void* d_out, int out_size) {
    const float* x = nullptr; const float* qkv_w = nullptr; const float* qkv_b = nullptr;
    const float* out_w = nullptr; const float* out_b = nullptr;
    for (int i = 0; i < n_in; i++) {
        switch (in_sizes[i]) {
            case 4194304: x     = (const float*)d_in[i]; break;
            case  196608: qkv_w = (const float*)d_in[i]; break;
            case     768: qkv_b = (const float*)d_in[i]; break;
            case   65536: out_w = (const float*)d_in[i]; break;
            case     256: out_b = (const float*)d_in[i]; break;
            default: break;
        }
    }
    float* out = (float*)d_out;

    cudaFuncSetAttribute(attn_kernel, cudaFuncAttributeMaxDynamicSharedMemorySize,
                         (int)sizeof(AttnSmem));

    qkv_kernel<<<dim3(N_TOK / 128, F3 / 64, B_SZ), 256>>>(x, qkv_w, qkv_b);
    attn_kernel<<<dim3(N_TOK / 64, B_SZ), 256, sizeof(AttnSmem)>>>();
    out_kernel<<<dim3(N_TOK / 128, EDIM / 64, B_SZ), 256>>>(x, out_w, out_b, out);
}

// round 8
// speedup vs baseline: 8.7650x; 2.0415x over previous
#include <cuda_runtime.h>
#include <cuda_bf16.h>
#include <math.h>
#include <stdint.h>

#define B_SZ   4
#define EDIM   256
#define N_TOK  4096
#define F3     768
#define SCL    0.0625f   // 1/sqrt(256)

// Scratch (allocation-free rule: __device__ globals)
__device__ __align__(16) __nv_bfloat16 g_qkvh[(size_t)B_SZ * N_TOK * F3]; // [b, n, 3E]
__device__ __align__(16) __nv_bfloat16 g_obh[(size_t)B_SZ * N_TOK * EDIM]; // [b, n, E]

__device__ __forceinline__ void ldsm_x4(uint32_t& r0, uint32_t& r1, uint32_t& r2, uint32_t& r3,
                                        uint32_t addr) {
    asm volatile("ldmatrix.sync.aligned.m8n8.x4.shared.b16 {%0,%1,%2,%3}, [%4];"
                 : "=r"(r0), "=r"(r1), "=r"(r2), "=r"(r3) : "r"(addr));
}
__device__ __forceinline__ void ldsm_x4_t(uint32_t& r0, uint32_t& r1, uint32_t& r2, uint32_t& r3,
                                          uint32_t addr) {
    asm volatile("ldmatrix.sync.aligned.m8n8.x4.trans.shared.b16 {%0,%1,%2,%3}, [%4];"
                 : "=r"(r0), "=r"(r1), "=r"(r2), "=r"(r3) : "r"(addr));
}
__device__ __forceinline__ void mma_bf16(float c[4], uint32_t a0, uint32_t a1, uint32_t a2,
                                         uint32_t a3, uint32_t b0, uint32_t b1) {
    asm volatile(
        "mma.sync.aligned.m16n8k16.row.col.f32.bf16.bf16.f32 "
        "{%0,%1,%2,%3}, {%4,%5,%6,%7}, {%8,%9}, {%0,%1,%2,%3};\n"
        : "+f"(c[0]), "+f"(c[1]), "+f"(c[2]), "+f"(c[3])
        : "r"(a0), "r"(a1), "r"(a2), "r"(a3), "r"(b0), "r"(b1));
}
__device__ __forceinline__ uint32_t sptr(const void* p) {
    return (uint32_t)__cvta_generic_to_shared(p);
}
// pack (lo, hi) floats into bf16x2 (lo in low half). cvt d,a,b: a->high, b->low
__device__ __forceinline__ uint32_t bf2pack(float lo, float hi) {
    uint32_t r;
    asm("cvt.rn.bf16x2.f32 %0, %1, %2;" : "=r"(r) : "f"(hi), "f"(lo));
    return r;
}
__device__ __forceinline__ void cp16(uint32_t dst, const void* src) {
    asm volatile("cp.async.cg.shared.global [%0], [%1], 16;" :: "r"(dst), "l"(src));
}
#define CP_COMMIT() asm volatile("cp.async.commit_group;")
#define CP_WAIT(n)  asm volatile("cp.async.wait_group %0;" :: "n"(n))

// ---------------------------------------------------------------------------
// Kernel 1: qkv[b, m, f] = sum_e x[b, e, m] * w[f, e] + bias[f]   (bf16 mma)
// ---------------------------------------------------------------------------
#define XS_STRIDE 136
#define WS_STRIDE 72

__global__ __launch_bounds__(256) void qkv_kernel(const float* __restrict__ x,
                                                  const float* __restrict__ w,
                                                  const float* __restrict__ bias) {
    __shared__ __nv_bfloat16 Xs[64][XS_STRIDE];   // [e][m]
    __shared__ __nv_bfloat16 Ws[64][WS_STRIDE];   // [f][e]
    const int tid  = threadIdx.x;
    const int lane = tid & 31;
    const int wp   = tid >> 5;
    const int g    = lane >> 2;
    const int t    = lane & 3;
    const int wm   = wp >> 1;
    const int wf   = wp & 1;
    const int mbase = blockIdx.x * 128;
    const int fbase = blockIdx.y * 64;
    const int b     = blockIdx.z;
    const float* xb = x + (size_t)b * EDIM * N_TOK;

    float c[2][4][4];
#pragma unroll
    for (int i = 0; i < 2; i++)
#pragma unroll
        for (int j = 0; j < 4; j++)
#pragma unroll
            for (int q = 0; q < 4; q++) c[i][j][q] = 0.f;

    const int at_row = (lane >> 4) * 8 + (lane & 7);
    const int at_col = ((lane >> 3) & 1) * 8;
    const int bk_row = wf * 32 + ((lane >> 4) & 1) * 8 + (lane & 7);
    const int bk_col = ((lane >> 3) & 1) * 8;

    for (int e0 = 0; e0 < EDIM; e0 += 64) {
        __syncthreads();
#pragma unroll
        for (int i = 0; i < 8; i++) {
            int lin = tid + i * 256;
            int e = lin >> 5, m4 = (lin & 31) * 4;
            float4 v = *(const float4*)(xb + (size_t)(e0 + e) * N_TOK + mbase + m4);
            uint32_t p0 = bf2pack(v.x, v.y), p1 = bf2pack(v.z, v.w);
            *(uint2*)(&Xs[e][m4]) = make_uint2(p0, p1);
        }
#pragma unroll
        for (int i = 0; i < 4; i++) {
            int lin = tid + i * 256;
            int f = lin >> 4, e4 = (lin & 15) * 4;
            float4 v = *(const float4*)(w + (size_t)(fbase + f) * EDIM + e0 + e4);
            uint32_t p0 = bf2pack(v.x, v.y), p1 = bf2pack(v.z, v.w);
            *(uint2*)(&Ws[f][e4]) = make_uint2(p0, p1);
        }
        __syncthreads();

#pragma unroll
        for (int ks = 0; ks < 4; ks++) {
            uint32_t a[2][4];
#pragma unroll
            for (int mi = 0; mi < 2; mi++)
                ldsm_x4_t(a[mi][0], a[mi][1], a[mi][2], a[mi][3],
                          sptr(&Xs[ks * 16 + at_row][wm * 32 + mi * 16 + at_col]));
#pragma unroll
            for (int p = 0; p < 2; p++) {
                uint32_t b0, b1, b2, b3;
                ldsm_x4(b0, b1, b2, b3, sptr(&Ws[bk_row + p * 16][ks * 16 + bk_col]));
#pragma unroll
                for (int mi = 0; mi < 2; mi++) {
                    mma_bf16(c[mi][2 * p],     a[mi][0], a[mi][1], a[mi][2], a[mi][3], b0, b1);
                    mma_bf16(c[mi][2 * p + 1], a[mi][0], a[mi][1], a[mi][2], a[mi][3], b2, b3);
                }
            }
        }
    }

#pragma unroll
    for (int ni = 0; ni < 4; ni++) {
        int f = fbase + wf * 32 + ni * 8 + 2 * t;
        float2 bb = *(const float2*)(bias + f);
#pragma unroll
        for (int mi = 0; mi < 2; mi++) {
            int m0 = mbase + wm * 32 + mi * 16 + g;
            uint32_t ptop = bf2pack(c[mi][ni][0] + bb.x, c[mi][ni][1] + bb.y);
            uint32_t pbot = bf2pack(c[mi][ni][2] + bb.x, c[mi][ni][3] + bb.y);
            *(uint32_t*)(&g_qkvh[((size_t)b * N_TOK + m0) * F3 + f])     = ptop;
            *(uint32_t*)(&g_qkvh[((size_t)b * N_TOK + m0 + 8) * F3 + f]) = pbot;
        }
    }
}

// ---------------------------------------------------------------------------
// Kernel 2: flash attention. Full-tile K/V via cp.async prefetch (1 tile ahead),
// softmax on mma fragments, 4 syncthreads per key tile.
// ---------------------------------------------------------------------------
#define QS_STRIDE 264   // bf16, 528B row, %128 == 16 -> conflict-free ldsm
#define PS_STRIDE 72

struct AttnSmem {
    __nv_bfloat16 Qs[64][QS_STRIDE];
    __nv_bfloat16 Ks[64][QS_STRIDE];
    __nv_bfloat16 Vs[64][QS_STRIDE];
    __nv_bfloat16 Ps[64][PS_STRIDE];
    float Mred[64][2];
    float Lred[64][2];
    float m_s[64], l_s[64];
};

__global__ __launch_bounds__(256, 2) void attn_kernel() {
    extern __shared__ char smem_raw[];
    AttnSmem& S = *reinterpret_cast<AttnSmem*>(smem_raw);

    const int tid  = threadIdx.x;
    const int lane = tid & 31;
    const int w    = tid >> 5;
    const int g    = lane >> 2;
    const int t    = lane & 3;
    const int rt16 = (w & 3) * 16;
    const int half = w >> 2;
    const int qbase = blockIdx.x * 64;
    const int b     = blockIdx.y;
    const __nv_bfloat16* qkv = g_qkvh + (size_t)b * N_TOK * F3;

    // cp.async chunk mapping: 2048 16B-chunks per 64x256 tile, 8 per thread
    // chunk c: row = c>>5, col = (c&31)*8
    const int top = rt16 + g, bot = rt16 + g + 8;

    // ---- prologue: issue K_0, load Q (plain), init state ----
#pragma unroll
    for (int i = 0; i < 8; i++) {
        int c = tid + i * 256;
        int row = c >> 5, col = (c & 31) * 8;
        cp16(sptr(&S.Ks[row][col]), qkv + (size_t)row * F3 + 256 + col);
    }
    CP_COMMIT();

    {
        const int ldrow = tid >> 2, ldq4 = tid & 3;
#pragma unroll
        for (int i = 0; i < 8; i++) {
            int col = ldq4 * 64 + i * 8;
            uint4 v = *(const uint4*)(qkv + (size_t)(qbase + ldrow) * F3 + col);
            *(uint4*)(&S.Qs[ldrow][col]) = v;
        }
    }
    if (tid < 64) { S.m_s[tid] = -INFINITY; S.l_s[tid] = 0.f; }

    float cO[16][4];
#pragma unroll
    for (int i = 0; i < 16; i++)
#pragma unroll
        for (int j = 0; j < 4; j++) cO[i][j] = 0.f;

    const int a_row   = rt16 + (lane & 15);
    const int a_coff  = (lane >> 4) * 8;
    const int bk_row  = half * 32 + ((lane >> 4) & 1) * 8 + (lane & 7);
    const int bk_coff = ((lane >> 3) & 1) * 8;
    const int bv_krow = ((lane >> 3) & 1) * 8 + (lane & 7);
    const int bv_doff = (lane >> 4) * 8;

    for (int kb = 0; kb < N_TOK; kb += 64) {
        // ---- entry: K_i ready; V buffer free ----
        CP_WAIT(0);
        __syncthreads();

        // issue V_i (overlaps S + softmax)
#pragma unroll
        for (int i = 0; i < 8; i++) {
            int c = tid + i * 256;
            int row = c >> 5, col = (c & 31) * 8;
            cp16(sptr(&S.Vs[row][col]), qkv + (size_t)(kb + row) * F3 + 512 + col);
        }
        CP_COMMIT();

        // ---- S = Q K^T, full tile, no internal syncs ----
        float cS[4][4];
#pragma unroll
        for (int n = 0; n < 4; n++)
#pragma unroll
            for (int j = 0; j < 4; j++) cS[n][j] = 0.f;

#pragma unroll
        for (int dc = 0; dc < 4; dc++) {
#pragma unroll
            for (int ks = 0; ks < 4; ks++) {
                int d0 = dc * 64 + ks * 16;
                uint32_t a0, a1, a2, a3;
                ldsm_x4(a0, a1, a2, a3, sptr(&S.Qs[a_row][d0 + a_coff]));
#pragma unroll
                for (int p = 0; p < 2; p++) {
                    uint32_t b0, b1, b2, b3;
                    ldsm_x4(b0, b1, b2, b3, sptr(&S.Ks[bk_row + p * 16][d0 + bk_coff]));
                    mma_bf16(cS[2 * p],     a0, a1, a2, a3, b0, b1);
                    mma_bf16(cS[2 * p + 1], a0, a1, a2, a3, b2, b3);
                }
            }
        }

        __syncthreads();   // S done everywhere -> K buffer free

        // issue K_{i+1} (overlaps softmax + PV); wrap harmlessly on last tile
        {
            int kb2 = (kb + 64) & (N_TOK - 1);
#pragma unroll
            for (int i = 0; i < 8; i++) {
                int c = tid + i * 256;
                int row = c >> 5, col = (c & 31) * 8;
                cp16(sptr(&S.Ks[row][col]), qkv + (size_t)(kb2 + row) * F3 + 256 + col);
            }
            CP_COMMIT();
        }

        // ---- softmax on fragments ----
        float mt = -INFINITY, mb = -INFINITY;
#pragma unroll
        for (int nt = 0; nt < 4; nt++) {
            cS[nt][0] *= SCL; cS[nt][1] *= SCL; cS[nt][2] *= SCL; cS[nt][3] *= SCL;
            mt = fmaxf(mt, fmaxf(cS[nt][0], cS[nt][1]));
            mb = fmaxf(mb, fmaxf(cS[nt][2], cS[nt][3]));
        }
        mt = fmaxf(mt, __shfl_xor_sync(0xffffffffu, mt, 1));
        mt = fmaxf(mt, __shfl_xor_sync(0xffffffffu, mt, 2));
        mb = fmaxf(mb, __shfl_xor_sync(0xffffffffu, mb, 1));
        mb = fmaxf(mb, __shfl_xor_sync(0xffffffffu, mb, 2));
        if (t == 0) { S.Mred[top][half] = mt; S.Mred[bot][half] = mb; }
        __syncthreads();   // Mred ready

        float mwt = fmaxf(S.Mred[top][0], S.Mred[top][1]);
        float mwb = fmaxf(S.Mred[bot][0], S.Mred[bot][1]);
        float moldt = S.m_s[top], moldb = S.m_s[bot];
        float mnt = fmaxf(moldt, mwt), mnb = fmaxf(moldb, mwb);
        float sct = __expf(moldt - mnt), scb = __expf(moldb - mnb);
        float st = 0.f, sb = 0.f;
#pragma unroll
        for (int nt = 0; nt < 4; nt++) {
            float e0 = __expf(cS[nt][0] - mnt), e1 = __expf(cS[nt][1] - mnt);
            float e2 = __expf(cS[nt][2] - mnb), e3 = __expf(cS[nt][3] - mnb);
            int col = half * 32 + nt * 8 + 2 * t;
            *(uint32_t*)(&S.Ps[top][col]) = bf2pack(e0, e1);
            *(uint32_t*)(&S.Ps[bot][col]) = bf2pack(e2, e3);
            st += e0 + e1; sb += e2 + e3;
        }
        st += __shfl_xor_sync(0xffffffffu, st, 1);
        st += __shfl_xor_sync(0xffffffffu, st, 2);
        sb += __shfl_xor_sync(0xffffffffu, sb, 1);
        sb += __shfl_xor_sync(0xffffffffu, sb, 2);
        if (t == 0) { S.Lred[top][half] = st; S.Lred[bot][half] = sb; }

        CP_WAIT(1);        // V_i done (K_{i+1} may still be in flight)
        __syncthreads();   // Ps/Lred ready + V visible

        if (half == 0 && t == 0) {
            S.m_s[top] = mnt;
            S.l_s[top] = S.l_s[top] * sct + S.Lred[top][0] + S.Lred[top][1];
            S.m_s[bot] = mnb;
            S.l_s[bot] = S.l_s[bot] * scb + S.Lred[bot][0] + S.Lred[bot][1];
        }

        // ---- PV: rescale O, then O += P V ----
#pragma unroll
        for (int nt = 0; nt < 16; nt++) {
            cO[nt][0] *= sct; cO[nt][1] *= sct;
            cO[nt][2] *= scb; cO[nt][3] *= scb;
        }
#pragma unroll
        for (int ks = 0; ks < 4; ks++) {
            uint32_t a0, a1, a2, a3;
            ldsm_x4(a0, a1, a2, a3, sptr(&S.Ps[a_row][ks * 16 + a_coff]));
#pragma unroll
            for (int p = 0; p < 8; p++) {
                uint32_t b0, b1, b2, b3;
                ldsm_x4_t(b0, b1, b2, b3,
                          sptr(&S.Vs[ks * 16 + bv_krow][half * 128 + p * 16 + bv_doff]));
                mma_bf16(cO[2 * p],     a0, a1, a2, a3, b0, b1);
                mma_bf16(cO[2 * p + 1], a0, a1, a2, a3, b2, b3);
            }
        }
    }

    __syncthreads();   // final l_s update visible

    // ---- normalize + write bf16 ----
    {
        float invt = 1.f / S.l_s[top];
        float invb = 1.f / S.l_s[bot];
        size_t bN = (size_t)b * N_TOK;
        int rowt = qbase + top;
        int rowb = qbase + bot;
#pragma unroll
        for (int nt = 0; nt < 16; nt++) {
            int col = half * 128 + nt * 8 + 2 * t;
            *(uint32_t*)(&g_obh[(bN + rowt) * EDIM + col]) =
                bf2pack(cO[nt][0] * invt, cO[nt][1] * invt);
            *(uint32_t*)(&g_obh[(bN + rowb) * EDIM + col]) =
                bf2pack(cO[nt][2] * invb, cO[nt][3] * invb);
        }
    }
}

// ---------------------------------------------------------------------------
// Kernel 3: out[b, e, m] = x + sum_k out_w[e,k] * o[m,k] + out_b[e]  (bf16 mma)
// ---------------------------------------------------------------------------
__global__ __launch_bounds__(256) void out_kernel(const float* __restrict__ x,
                                                  const float* __restrict__ w,
                                                  const float* __restrict__ bias,
                                                  float* __restrict__ out) {
    __shared__ __nv_bfloat16 Ws2[64][WS_STRIDE];   // [e][k]
    __shared__ __nv_bfloat16 Os[128][WS_STRIDE];   // [m][k]
    const int tid  = threadIdx.x;
    const int lane = tid & 31;
    const int wp   = tid >> 5;
    const int g    = lane >> 2;
    const int t    = lane & 3;
    const int we   = wp & 1;
    const int wm   = wp >> 1;
    const int mbase = blockIdx.x * 128;
    const int ebase = blockIdx.y * 64;
    const int b     = blockIdx.z;

    float c[2][4][4];
#pragma unroll
    for (int i = 0; i < 2; i++)
#pragma unroll
        for (int j = 0; j < 4; j++)
#pragma unroll
            for (int q = 0; q < 4; q++) c[i][j][q] = 0.f;

    const int a_row  = we * 32 + (lane & 15);
    const int a_coff = (lane >> 4) * 8;
    const int b_row  = wm * 32 + ((lane >> 4) & 1) * 8 + (lane & 7);
    const int b_coff = ((lane >> 3) & 1) * 8;

    for (int k0 = 0; k0 < EDIM; k0 += 64) {
        __syncthreads();
#pragma unroll
        for (int i = 0; i < 4; i++) {
            int lin = tid + i * 256;
            int e = lin >> 4, k4 = (lin & 15) * 4;
            float4 v = *(const float4*)(w + (size_t)(ebase + e) * EDIM + k0 + k4);
            uint32_t p0 = bf2pack(v.x, v.y), p1 = bf2pack(v.z, v.w);
            *(uint2*)(&Ws2[e][k4]) = make_uint2(p0, p1);
        }
#pragma unroll
        for (int i = 0; i < 4; i++) {
            int lin = tid + i * 256;
            int m = lin >> 3, k8 = (lin & 7) * 8;
            uint4 v = *(const uint4*)(g_obh + ((size_t)b * N_TOK + mbase + m) * EDIM + k0 + k8);
            *(uint4*)(&Os[m][k8]) = v;
        }
        __syncthreads();

#pragma unroll
        for (int ks = 0; ks < 4; ks++) {
            uint32_t a[2][4];
#pragma unroll
            for (int mi = 0; mi < 2; mi++)
                ldsm_x4(a[mi][0], a[mi][1], a[mi][2], a[mi][3],
                        sptr(&Ws2[a_row + mi * 16][ks * 16 + a_coff]));
#pragma unroll
            for (int p = 0; p < 2; p++) {
                uint32_t b0, b1, b2, b3;
                ldsm_x4(b0, b1, b2, b3, sptr(&Os[b_row + p * 16][ks * 16 + b_coff]));
#pragma unroll
                for (int mi = 0; mi < 2; mi++) {
                    mma_bf16(c[mi][2 * p],     a[mi][0], a[mi][1], a[mi][2], a[mi][3], b0, b1);
                    mma_bf16(c[mi][2 * p + 1], a[mi][0], a[mi][1], a[mi][2], a[mi][3], b2, b3);
                }
            }
        }
    }

#pragma unroll
    for (int mi = 0; mi < 2; mi++) {
        int e0 = ebase + we * 32 + mi * 16 + g;
        float bt = bias[e0], bb = bias[e0 + 8];
#pragma unroll
        for (int ni = 0; ni < 4; ni++) {
            int m = mbase + wm * 32 + ni * 8 + 2 * t;
            size_t it = ((size_t)b * EDIM + e0) * N_TOK + m;
            size_t ib = ((size_t)b * EDIM + e0 + 8) * N_TOK + m;
            float2 xt = *(const float2*)(x + it);
            float2 xb = *(const float2*)(x + ib);
            *(float2*)(out + it) = make_float2(xt.x + c[mi][ni][0] + bt,
                                               xt.y + c[mi][ni][1] + bt);
            *(float2*)(out + ib) = make_float2(xb.x + c[mi][ni][2] + bb,
                                               xb.y + c[mi][ni][3] + bb);
        }
    }
}

// ---------------------------------------------------------------------------
extern "C" void kernel_launch(void* const* d_in, const int* in_sizes, int n_in,
                              void* d_out, int out_size) {
    const float* x = nullptr; const float* qkv_w = nullptr; const float* qkv_b = nullptr;
    const float* out_w = nullptr; const float* out_b = nullptr;
    for (int i = 0; i < n_in; i++) {
        switch (in_sizes[i]) {
            case 4194304: x     = (const float*)d_in[i]; break;
            case  196608: qkv_w = (const float*)d_in[i]; break;
            case     768: qkv_b = (const float*)d_in[i]; break;
            case   65536: out_w = (const float*)d_in[i]; break;
            case     256: out_b = (const float*)d_in[i]; break;
            default: break;
        }
    }
    float* out = (float*)d_out;

    cudaFuncSetAttribute(attn_kernel, cudaFuncAttributeMaxDynamicSharedMemorySize,
                         (int)sizeof(AttnSmem));

    qkv_kernel<<<dim3(N_TOK / 128, F3 / 64, B_SZ), 256>>>(x, qkv_w, qkv_b);
    attn_kernel<<<dim3(N_TOK / 64, B_SZ), 256, sizeof(AttnSmem)>>>();
    out_kernel<<<dim3(N_TOK / 128, EDIM / 64, B_SZ), 256>>>(x, out_w, out_b, out);
}

// round 11
// speedup vs baseline: 8.8430x; 1.0089x over previous
#include <cuda_runtime.h>
#include <cuda_bf16.h>
#include <math.h>
#include <stdint.h>

#define B_SZ   4
#define EDIM   256
#define N_TOK  4096
#define F3     768
#define SCL    0.0625f   // 1/sqrt(256)

// Scratch (allocation-free rule: __device__ globals)
__device__ __align__(16) __nv_bfloat16 g_qkvh[(size_t)B_SZ * N_TOK * F3]; // [b, n, 3E]
__device__ __align__(16) __nv_bfloat16 g_obh[(size_t)B_SZ * N_TOK * EDIM]; // [b, n, E]

__device__ __forceinline__ void ldsm_x4(uint32_t& r0, uint32_t& r1, uint32_t& r2, uint32_t& r3,
                                        uint32_t addr) {
    asm volatile("ldmatrix.sync.aligned.m8n8.x4.shared.b16 {%0,%1,%2,%3}, [%4];"
                 : "=r"(r0), "=r"(r1), "=r"(r2), "=r"(r3) : "r"(addr));
}
__device__ __forceinline__ void ldsm_x4_t(uint32_t& r0, uint32_t& r1, uint32_t& r2, uint32_t& r3,
                                          uint32_t addr) {
    asm volatile("ldmatrix.sync.aligned.m8n8.x4.trans.shared.b16 {%0,%1,%2,%3}, [%4];"
                 : "=r"(r0), "=r"(r1), "=r"(r2), "=r"(r3) : "r"(addr));
}
__device__ __forceinline__ void mma_bf16(float c[4], uint32_t a0, uint32_t a1, uint32_t a2,
                                         uint32_t a3, uint32_t b0, uint32_t b1) {
    asm volatile(
        "mma.sync.aligned.m16n8k16.row.col.f32.bf16.bf16.f32 "
        "{%0,%1,%2,%3}, {%4,%5,%6,%7}, {%8,%9}, {%0,%1,%2,%3};\n"
        : "+f"(c[0]), "+f"(c[1]), "+f"(c[2]), "+f"(c[3])
        : "r"(a0), "r"(a1), "r"(a2), "r"(a3), "r"(b0), "r"(b1));
}
__device__ __forceinline__ uint32_t sptr(const void* p) {
    return (uint32_t)__cvta_generic_to_shared(p);
}
// pack (lo, hi) floats into bf16x2 (lo in low half). cvt d,a,b: a->high, b->low
__device__ __forceinline__ uint32_t bf2pack(float lo, float hi) {
    uint32_t r;
    asm("cvt.rn.bf16x2.f32 %0, %1, %2;" : "=r"(r) : "f"(hi), "f"(lo));
    return r;
}
__device__ __forceinline__ void cp16(uint32_t dst, const void* src) {
    asm volatile("cp.async.cg.shared.global [%0], [%1], 16;" :: "r"(dst), "l"(src));
}
#define CP_COMMIT() asm volatile("cp.async.commit_group;")
#define CP_WAIT(n)  asm volatile("cp.async.wait_group %0;" :: "n"(n))

#define XS_STRIDE 136   // 272B % 128 == 16 -> conflict-free ldsm
#define KS_STRIDE 72    // 144B % 128 == 16

// ---------------------------------------------------------------------------
// Kernel 1: qkv[b, m, f] = sum_e x[b, e, m] * w[f, e] + bias[f]   (bf16 mma)
// CTA: 128 m x 128 f, k-chunk 64. Warps 4(m) x 2(f), warp tile 32m x 64f.
// ---------------------------------------------------------------------------
__global__ __launch_bounds__(256, 2) void qkv_kernel(const float* __restrict__ x,
                                                     const float* __restrict__ w,
                                                     const float* __restrict__ bias) {
    __shared__ __nv_bfloat16 Xs[64][XS_STRIDE];    // [e][m] (m up to 128)
    __shared__ __nv_bfloat16 Ws[128][KS_STRIDE];   // [f][e] (e chunk 64)
    const int tid  = threadIdx.x;
    const int lane = tid & 31;
    const int wp   = tid >> 5;
    const int g    = lane >> 2;
    const int t    = lane & 3;
    const int wm   = wp >> 1;           // 0..3 : m-subtile of 32
    const int wf   = wp & 1;            // 0..1 : f-subtile of 64
    const int mbase = blockIdx.x * 128;
    const int fbase = blockIdx.y * 128;
    const int b     = blockIdx.z;
    const float* xb = x + (size_t)b * EDIM * N_TOK;

    float c[2][8][4];
#pragma unroll
    for (int i = 0; i < 2; i++)
#pragma unroll
        for (int j = 0; j < 8; j++)
#pragma unroll
            for (int q = 0; q < 4; q++) c[i][j][q] = 0.f;

    const int at_row = (lane >> 4) * 8 + (lane & 7);        // A-trans: e-offset
    const int at_col = ((lane >> 3) & 1) * 8;               // A-trans: m-offset
    const int bk_row = wf * 64 + ((lane >> 4) & 1) * 8 + (lane & 7);  // B: f-row
    const int bk_col = ((lane >> 3) & 1) * 8;               // B: e-offset

    for (int e0 = 0; e0 < EDIM; e0 += 64) {
        __syncthreads();
        // Xs[e][m]: 64 x 128, coalesced along m
#pragma unroll
        for (int i = 0; i < 8; i++) {
            int lin = tid + i * 256;
            int e = lin >> 5, m4 = (lin & 31) * 4;
            float4 v = *(const float4*)(xb + (size_t)(e0 + e) * N_TOK + mbase + m4);
            uint32_t p0 = bf2pack(v.x, v.y), p1 = bf2pack(v.z, v.w);
            *(uint2*)(&Xs[e][m4]) = make_uint2(p0, p1);
        }
        // Ws[f][e]: 128 x 64
#pragma unroll
        for (int i = 0; i < 8; i++) {
            int lin = tid + i * 256;
            int f = lin >> 4, e4 = (lin & 15) * 4;
            float4 v = *(const float4*)(w + (size_t)(fbase + f) * EDIM + e0 + e4);
            uint32_t p0 = bf2pack(v.x, v.y), p1 = bf2pack(v.z, v.w);
            *(uint2*)(&Ws[f][e4]) = make_uint2(p0, p1);
        }
        __syncthreads();

#pragma unroll
        for (int ks = 0; ks < 4; ks++) {
            uint32_t a[2][4];
#pragma unroll
            for (int mi = 0; mi < 2; mi++)
                ldsm_x4_t(a[mi][0], a[mi][1], a[mi][2], a[mi][3],
                          sptr(&Xs[ks * 16 + at_row][wm * 32 + mi * 16 + at_col]));
#pragma unroll
            for (int p = 0; p < 4; p++) {
                uint32_t b0, b1, b2, b3;
                ldsm_x4(b0, b1, b2, b3, sptr(&Ws[bk_row + p * 16][ks * 16 + bk_col]));
#pragma unroll
                for (int mi = 0; mi < 2; mi++) {
                    mma_bf16(c[mi][2 * p],     a[mi][0], a[mi][1], a[mi][2], a[mi][3], b0, b1);
                    mma_bf16(c[mi][2 * p + 1], a[mi][0], a[mi][1], a[mi][2], a[mi][3], b2, b3);
                }
            }
        }
    }

    // epilogue: + bias, bf16 pack, store [m][f]
#pragma unroll
    for (int ni = 0; ni < 8; ni++) {
        int f = fbase + wf * 64 + ni * 8 + 2 * t;
        float2 bb = *(const float2*)(bias + f);
#pragma unroll
        for (int mi = 0; mi < 2; mi++) {
            int m0 = mbase + wm * 32 + mi * 16 + g;
            uint32_t ptop = bf2pack(c[mi][ni][0] + bb.x, c[mi][ni][1] + bb.y);
            uint32_t pbot = bf2pack(c[mi][ni][2] + bb.x, c[mi][ni][3] + bb.y);
            *(uint32_t*)(&g_qkvh[((size_t)b * N_TOK + m0) * F3 + f])     = ptop;
            *(uint32_t*)(&g_qkvh[((size_t)b * N_TOK + m0 + 8) * F3 + f]) = pbot;
        }
    }
}

// ---------------------------------------------------------------------------
// Kernel 2: flash attention. cp.async prefetch, fragment softmax.
// S phase : warp (rt=w&3, half=w>>2): 16 rows x 32 k-cols.
// PV phase: warp (rt2=w&1, dq=w>>1): 32 rows x 64 d-cols (B reads halved).
// ---------------------------------------------------------------------------
#define QS_STRIDE 264   // bf16, 528B row, %128 == 16 -> conflict-free ldsm

struct AttnSmem {
    __nv_bfloat16 Qs[64][QS_STRIDE];
    __nv_bfloat16 Ks[64][QS_STRIDE];
    __nv_bfloat16 Vs[64][QS_STRIDE];
    __nv_bfloat16 Ps[64][KS_STRIDE];
    float Mred[64][2];
    float Lred[64][2];
    float m_s[64], l_s[64], scr[64];
};

__global__ __launch_bounds__(256, 2) void attn_kernel() {
    extern __shared__ char smem_raw[];
    AttnSmem& S = *reinterpret_cast<AttnSmem*>(smem_raw);

    const int tid  = threadIdx.x;
    const int lane = tid & 31;
    const int w    = tid >> 5;
    const int g    = lane >> 2;
    const int t    = lane & 3;
    const int rt16 = (w & 3) * 16;      // S-phase row tile
    const int half = w >> 2;            // S-phase k half
    const int rt2  = w & 1;             // PV row group (32 rows)
    const int dq   = w >> 1;            // PV d quarter (64 cols)
    const int qbase = blockIdx.x * 64;
    const int b     = blockIdx.y;
    const __nv_bfloat16* qkv = g_qkvh + (size_t)b * N_TOK * F3;

    const int top = rt16 + g, bot = rt16 + g + 8;

    // ---- prologue: issue K_0, load Q (plain), init state ----
#pragma unroll
    for (int i = 0; i < 8; i++) {
        int c = tid + i * 256;
        int row = c >> 5, col = (c & 31) * 8;
        cp16(sptr(&S.Ks[row][col]), qkv + (size_t)row * F3 + 256 + col);
    }
    CP_COMMIT();

    {
        const int ldrow = tid >> 2, ldq4 = tid & 3;
#pragma unroll
        for (int i = 0; i < 8; i++) {
            int col = ldq4 * 64 + i * 8;
            uint4 v = *(const uint4*)(qkv + (size_t)(qbase + ldrow) * F3 + col);
            *(uint4*)(&S.Qs[ldrow][col]) = v;
        }
    }
    if (tid < 64) { S.m_s[tid] = -INFINITY; S.l_s[tid] = 0.f; }

    float cO[2][8][4];
#pragma unroll
    for (int mi = 0; mi < 2; mi++)
#pragma unroll
        for (int i = 0; i < 8; i++)
#pragma unroll
            for (int j = 0; j < 4; j++) cO[mi][i][j] = 0.f;

    // S-phase addresses
    const int a_row   = rt16 + (lane & 15);
    const int a_coff  = (lane >> 4) * 8;
    const int bk_row  = half * 32 + ((lane >> 4) & 1) * 8 + (lane & 7);
    const int bk_coff = ((lane >> 3) & 1) * 8;
    // PV addresses
    const int pv_arow = rt2 * 32 + (lane & 15);
    const int bv_krow = ((lane >> 3) & 1) * 8 + (lane & 7);
    const int bv_doff = (lane >> 4) * 8;

    for (int kb = 0; kb < N_TOK; kb += 64) {
        // ---- entry: K_i ready; V buffer free ----
        CP_WAIT(0);
        __syncthreads();

        // issue V_i (overlaps S + softmax)
#pragma unroll
        for (int i = 0; i < 8; i++) {
            int c = tid + i * 256;
            int row = c >> 5, col = (c & 31) * 8;
            cp16(sptr(&S.Vs[row][col]), qkv + (size_t)(kb + row) * F3 + 512 + col);
        }
        CP_COMMIT();

        // ---- S = Q K^T, full tile, no internal syncs ----
        float cS[4][4];
#pragma unroll
        for (int n = 0; n < 4; n++)
#pragma unroll
            for (int j = 0; j < 4; j++) cS[n][j] = 0.f;

#pragma unroll
        for (int dc = 0; dc < 4; dc++) {
#pragma unroll
            for (int ks = 0; ks < 4; ks++) {
                int d0 = dc * 64 + ks * 16;
                uint32_t a0, a1, a2, a3;
                ldsm_x4(a0, a1, a2, a3, sptr(&S.Qs[a_row][d0 + a_coff]));
#pragma unroll
                for (int p = 0; p < 2; p++) {
                    uint32_t b0, b1, b2, b3;
                    ldsm_x4(b0, b1, b2, b3, sptr(&S.Ks[bk_row + p * 16][d0 + bk_coff]));
                    mma_bf16(cS[2 * p],     a0, a1, a2, a3, b0, b1);
                    mma_bf16(cS[2 * p + 1], a0, a1, a2, a3, b2, b3);
                }
            }
        }

        __syncthreads();   // S done everywhere -> K buffer free

        // issue K_{i+1} (overlaps softmax + PV); wrap harmlessly on last tile
        {
            int kb2 = (kb + 64) & (N_TOK - 1);
#pragma unroll
            for (int i = 0; i < 8; i++) {
                int c = tid + i * 256;
                int row = c >> 5, col = (c & 31) * 8;
                cp16(sptr(&S.Ks[row][col]), qkv + (size_t)(kb2 + row) * F3 + 256 + col);
            }
            CP_COMMIT();
        }

        // ---- softmax on fragments ----
        float mt = -INFINITY, mb = -INFINITY;
#pragma unroll
        for (int nt = 0; nt < 4; nt++) {
            cS[nt][0] *= SCL; cS[nt][1] *= SCL; cS[nt][2] *= SCL; cS[nt][3] *= SCL;
            mt = fmaxf(mt, fmaxf(cS[nt][0], cS[nt][1]));
            mb = fmaxf(mb, fmaxf(cS[nt][2], cS[nt][3]));
        }
        mt = fmaxf(mt, __shfl_xor_sync(0xffffffffu, mt, 1));
        mt = fmaxf(mt, __shfl_xor_sync(0xffffffffu, mt, 2));
        mb = fmaxf(mb, __shfl_xor_sync(0xffffffffu, mb, 1));
        mb = fmaxf(mb, __shfl_xor_sync(0xffffffffu, mb, 2));
        if (t == 0) { S.Mred[top][half] = mt; S.Mred[bot][half] = mb; }
        __syncthreads();   // Mred ready

        float mwt = fmaxf(S.Mred[top][0], S.Mred[top][1]);
        float mwb = fmaxf(S.Mred[bot][0], S.Mred[bot][1]);
        float moldt = S.m_s[top], moldb = S.m_s[bot];
        float mnt = fmaxf(moldt, mwt), mnb = fmaxf(moldb, mwb);
        float sct = __expf(moldt - mnt), scb = __expf(moldb - mnb);
        float st = 0.f, sb = 0.f;
#pragma unroll
        for (int nt = 0; nt < 4; nt++) {
            float e0 = __expf(cS[nt][0] - mnt), e1 = __expf(cS[nt][1] - mnt);
            float e2 = __expf(cS[nt][2] - mnb), e3 = __expf(cS[nt][3] - mnb);
            int col = half * 32 + nt * 8 + 2 * t;
            *(uint32_t*)(&S.Ps[top][col]) = bf2pack(e0, e1);
            *(uint32_t*)(&S.Ps[bot][col]) = bf2pack(e2, e3);
            st += e0 + e1; sb += e2 + e3;
        }
        st += __shfl_xor_sync(0xffffffffu, st, 1);
        st += __shfl_xor_sync(0xffffffffu, st, 2);
        sb += __shfl_xor_sync(0xffffffffu, sb, 1);
        sb += __shfl_xor_sync(0xffffffffu, sb, 2);
        if (t == 0) {
            S.Lred[top][half] = st; S.Lred[bot][half] = sb;
            S.scr[top] = sct;       S.scr[bot] = scb;     // same value both halves
        }

        CP_WAIT(1);        // V_i done (K_{i+1} may still be in flight)
        __syncthreads();   // Ps/Lred/scr ready + V visible

        if (half == 0 && t == 0) {
            S.m_s[top] = mnt;
            S.l_s[top] = S.l_s[top] * sct + S.Lred[top][0] + S.Lred[top][1];
            S.m_s[bot] = mnb;
            S.l_s[bot] = S.l_s[bot] * scb + S.Lred[bot][0] + S.Lred[bot][1];
        }

        // ---- PV: warp = 32 rows (rt2) x 64 d (dq) ----
        {
            float s00 = S.scr[rt2 * 32 + g],      s01 = S.scr[rt2 * 32 + g + 8];
            float s10 = S.scr[rt2 * 32 + 16 + g], s11 = S.scr[rt2 * 32 + 16 + g + 8];
#pragma unroll
            for (int ni = 0; ni < 8; ni++) {
                cO[0][ni][0] *= s00; cO[0][ni][1] *= s00;
                cO[0][ni][2] *= s01; cO[0][ni][3] *= s01;
                cO[1][ni][0] *= s10; cO[1][ni][1] *= s10;
                cO[1][ni][2] *= s11; cO[1][ni][3] *= s11;
            }
        }
#pragma unroll
        for (int ks = 0; ks < 4; ks++) {
            uint32_t a[2][4];
#pragma unroll
            for (int mi = 0; mi < 2; mi++)
                ldsm_x4(a[mi][0], a[mi][1], a[mi][2], a[mi][3],
                        sptr(&S.Ps[pv_arow + mi * 16][ks * 16 + a_coff]));
#pragma unroll
            for (int p = 0; p < 4; p++) {
                uint32_t b0, b1, b2, b3;
                ldsm_x4_t(b0, b1, b2, b3,
                          sptr(&S.Vs[ks * 16 + bv_krow][dq * 64 + p * 16 + bv_doff]));
#pragma unroll
                for (int mi = 0; mi < 2; mi++) {
                    mma_bf16(cO[mi][2 * p],     a[mi][0], a[mi][1], a[mi][2], a[mi][3], b0, b1);
                    mma_bf16(cO[mi][2 * p + 1], a[mi][0], a[mi][1], a[mi][2], a[mi][3], b2, b3);
                }
            }
        }
    }

    __syncthreads();   // final l_s update visible

    // ---- normalize + write bf16: rows rt2*32 + mi*16 + g(+8), cols dq*64.. ----
    {
        size_t bN = (size_t)b * N_TOK;
#pragma unroll
        for (int mi = 0; mi < 2; mi++) {
            int r0 = rt2 * 32 + mi * 16 + g;
            float inv0 = 1.f / S.l_s[r0];
            float inv1 = 1.f / S.l_s[r0 + 8];
            size_t row0 = (bN + qbase + r0) * EDIM;
            size_t row1 = (bN + qbase + r0 + 8) * EDIM;
#pragma unroll
            for (int ni = 0; ni < 8; ni++) {
                int col = dq * 64 + ni * 8 + 2 * t;
                *(uint32_t*)(&g_obh[row0 + col]) =
                    bf2pack(cO[mi][ni][0] * inv0, cO[mi][ni][1] * inv0);
                *(uint32_t*)(&g_obh[row1 + col]) =
                    bf2pack(cO[mi][ni][2] * inv1, cO[mi][ni][3] * inv1);
            }
        }
    }
}

// ---------------------------------------------------------------------------
// Kernel 3: out[b, e, m] = x + sum_k out_w[e,k] * o[m,k] + out_b[e]  (bf16 mma)
// CTA: 128 e x 128 m, k-chunk 64. Warps 4(e) x 2(m), warp tile 32e x 64m.
// ---------------------------------------------------------------------------
__global__ __launch_bounds__(256, 2) void out_kernel(const float* __restrict__ x,
                                                     const float* __restrict__ w,
                                                     const float* __restrict__ bias,
                                                     float* __restrict__ out) {
    __shared__ __nv_bfloat16 Ws2[128][KS_STRIDE];  // [e][k]
    __shared__ __nv_bfloat16 Os[128][KS_STRIDE];   // [m][k]
    const int tid  = threadIdx.x;
    const int lane = tid & 31;
    const int wp   = tid >> 5;
    const int g    = lane >> 2;
    const int t    = lane & 3;
    const int we   = wp >> 1;           // 0..3 : e-subtile of 32
    const int wm   = wp & 1;            // 0..1 : m-subtile of 64
    const int mbase = blockIdx.x * 128;
    const int ebase = blockIdx.y * 128;
    const int b     = blockIdx.z;

    float c[2][8][4];
#pragma unroll
    for (int i = 0; i < 2; i++)
#pragma unroll
        for (int j = 0; j < 8; j++)
#pragma unroll
            for (int q = 0; q < 4; q++) c[i][j][q] = 0.f;

    const int a_row  = we * 32 + (lane & 15);
    const int a_coff = (lane >> 4) * 8;
    const int b_row  = wm * 64 + ((lane >> 4) & 1) * 8 + (lane & 7);
    const int b_coff = ((lane >> 3) & 1) * 8;

    for (int k0 = 0; k0 < EDIM; k0 += 64) {
        __syncthreads();
        // Ws2[e][k]: 128 x 64 fp32 -> bf16
#pragma unroll
        for (int i = 0; i < 8; i++) {
            int lin = tid + i * 256;
            int e = lin >> 4, k4 = (lin & 15) * 4;
            float4 v = *(const float4*)(w + (size_t)(ebase + e) * EDIM + k0 + k4);
            uint32_t p0 = bf2pack(v.x, v.y), p1 = bf2pack(v.z, v.w);
            *(uint2*)(&Ws2[e][k4]) = make_uint2(p0, p1);
        }
        // Os[m][k]: 128 x 64 bf16
#pragma unroll
        for (int i = 0; i < 4; i++) {
            int lin = tid + i * 256;
            int m = lin >> 3, k8 = (lin & 7) * 8;
            uint4 v = *(const uint4*)(g_obh + ((size_t)b * N_TOK + mbase + m) * EDIM + k0 + k8);
            *(uint4*)(&Os[m][k8]) = v;
        }
        __syncthreads();

#pragma unroll
        for (int ks = 0; ks < 4; ks++) {
            uint32_t a[2][4];
#pragma unroll
            for (int mi = 0; mi < 2; mi++)
                ldsm_x4(a[mi][0], a[mi][1], a[mi][2], a[mi][3],
                        sptr(&Ws2[a_row + mi * 16][ks * 16 + a_coff]));
#pragma unroll
            for (int p = 0; p < 4; p++) {
                uint32_t b0, b1, b2, b3;
                ldsm_x4(b0, b1, b2, b3, sptr(&Os[b_row + p * 16][ks * 16 + b_coff]));
#pragma unroll
                for (int mi = 0; mi < 2; mi++) {
                    mma_bf16(c[mi][2 * p],     a[mi][0], a[mi][1], a[mi][2], a[mi][3], b0, b1);
                    mma_bf16(c[mi][2 * p + 1], a[mi][0], a[mi][1], a[mi][2], a[mi][3], b2, b3);
                }
            }
        }
    }

    // epilogue: residual + bias, fp32 out [e][m]
#pragma unroll
    for (int mi = 0; mi < 2; mi++) {
        int e0 = ebase + we * 32 + mi * 16 + g;
        float bt = bias[e0], bb = bias[e0 + 8];
#pragma unroll
        for (int ni = 0; ni < 8; ni++) {
            int m = mbase + wm * 64 + ni * 8 + 2 * t;
            size_t it = ((size_t)b * EDIM + e0) * N_TOK + m;
            size_t ib = ((size_t)b * EDIM + e0 + 8) * N_TOK + m;
            float2 xt = *(const float2*)(x + it);
            float2 xb = *(const float2*)(x + ib);
            *(float2*)(out + it) = make_float2(xt.x + c[mi][ni][0] + bt,
                                               xt.y + c[mi][ni][1] + bt);
            *(float2*)(out + ib) = make_float2(xb.x + c[mi][ni][2] + bb,
                                               xb.y + c[mi][ni][3] + bb);
        }
    }
}

// ---------------------------------------------------------------------------
extern "C" void kernel_launch(void* const* d_in, const int* in_sizes, int n_in,
                              void* d_out, int out_size) {
    const float* x = nullptr; const float* qkv_w = nullptr; const float* qkv_b = nullptr;
    const float* out_w = nullptr; const float* out_b = nullptr;
    for (int i = 0; i < n_in; i++) {
        switch (in_sizes[i]) {
            case 4194304: x     = (const float*)d_in[i]; break;
            case  196608: qkv_w = (const float*)d_in[i]; break;
            case     768: qkv_b = (const float*)d_in[i]; break;
            case   65536: out_w = (const float*)d_in[i]; break;
            case     256: out_b = (const float*)d_in[i]; break;
            default: break;
        }
    }
    float* out = (float*)d_out;

    cudaFuncSetAttribute(attn_kernel, cudaFuncAttributeMaxDynamicSharedMemorySize,
                         (int)sizeof(AttnSmem));

    qkv_kernel<<<dim3(N_TOK / 128, F3 / 128, B_SZ), 256>>>(x, qkv_w, qkv_b);
    attn_kernel<<<dim3(N_TOK / 64, B_SZ), 256, sizeof(AttnSmem)>>>();
    out_kernel<<<dim3(N_TOK / 128, EDIM / 128, B_SZ), 256>>>(x, out_w, out_b, out);
}

// round 12
// speedup vs baseline: 8.8586x; 1.0018x over previous
#include <cuda_runtime.h>
#include <cuda_bf16.h>
#include <math.h>
#include <stdint.h>

#define B_SZ   4
#define EDIM   256
#define N_TOK  4096
#define F3     768
#define SCL    0.0625f   // 1/sqrt(256)

// Scratch (allocation-free rule: __device__ globals)
__device__ __align__(16) __nv_bfloat16 g_qkvh[(size_t)B_SZ * N_TOK * F3]; // [b, n, 3E]
__device__ __align__(16) __nv_bfloat16 g_obh[(size_t)B_SZ * N_TOK * EDIM]; // [b, n, E]

__device__ __forceinline__ void ldsm_x4(uint32_t& r0, uint32_t& r1, uint32_t& r2, uint32_t& r3,
                                        uint32_t addr) {
    asm volatile("ldmatrix.sync.aligned.m8n8.x4.shared.b16 {%0,%1,%2,%3}, [%4];"
                 : "=r"(r0), "=r"(r1), "=r"(r2), "=r"(r3) : "r"(addr));
}
__device__ __forceinline__ void ldsm_x4_t(uint32_t& r0, uint32_t& r1, uint32_t& r2, uint32_t& r3,
                                          uint32_t addr) {
    asm volatile("ldmatrix.sync.aligned.m8n8.x4.trans.shared.b16 {%0,%1,%2,%3}, [%4];"
                 : "=r"(r0), "=r"(r1), "=r"(r2), "=r"(r3) : "r"(addr));
}
__device__ __forceinline__ void mma_bf16(float c[4], uint32_t a0, uint32_t a1, uint32_t a2,
                                         uint32_t a3, uint32_t b0, uint32_t b1) {
    asm volatile(
        "mma.sync.aligned.m16n8k16.row.col.f32.bf16.bf16.f32 "
        "{%0,%1,%2,%3}, {%4,%5,%6,%7}, {%8,%9}, {%0,%1,%2,%3};\n"
        : "+f"(c[0]), "+f"(c[1]), "+f"(c[2]), "+f"(c[3])
        : "r"(a0), "r"(a1), "r"(a2), "r"(a3), "r"(b0), "r"(b1));
}
__device__ __forceinline__ uint32_t sptr(const void* p) {
    return (uint32_t)__cvta_generic_to_shared(p);
}
// pack (lo, hi) floats into bf16x2 (lo in low half). cvt d,a,b: a->high, b->low
__device__ __forceinline__ uint32_t bf2pack(float lo, float hi) {
    uint32_t r;
    asm("cvt.rn.bf16x2.f32 %0, %1, %2;" : "=r"(r) : "f"(hi), "f"(lo));
    return r;
}
__device__ __forceinline__ void cp16(uint32_t dst, const void* src) {
    asm volatile("cp.async.cg.shared.global [%0], [%1], 16;" :: "r"(dst), "l"(src));
}
#define CP_COMMIT() asm volatile("cp.async.commit_group;")
#define CP_WAIT(n)  asm volatile("cp.async.wait_group %0;" :: "n"(n))

#define XS_STRIDE 136   // 272B % 128 == 16 -> conflict-free ldsm
#define KS_STRIDE 72    // 144B % 128 == 16

// ---------------------------------------------------------------------------
// Kernel 1: qkv[b, m, f] = sum_e x[b, e, m] * w[f, e] + bias[f]   (bf16 mma)
// CTA: 128 m x 128 f, k-chunk 64. Warps 4(m) x 2(f), warp tile 32m x 64f.
// ---------------------------------------------------------------------------
__global__ __launch_bounds__(256, 2) void qkv_kernel(const float* __restrict__ x,
                                                     const float* __restrict__ w,
                                                     const float* __restrict__ bias) {
    __shared__ __nv_bfloat16 Xs[64][XS_STRIDE];    // [e][m] (m up to 128)
    __shared__ __nv_bfloat16 Ws[128][KS_STRIDE];   // [f][e] (e chunk 64)
    const int tid  = threadIdx.x;
    const int lane = tid & 31;
    const int wp   = tid >> 5;
    const int g    = lane >> 2;
    const int t    = lane & 3;
    const int wm   = wp >> 1;           // 0..3 : m-subtile of 32
    const int wf   = wp & 1;            // 0..1 : f-subtile of 64
    const int mbase = blockIdx.x * 128;
    const int fbase = blockIdx.y * 128;
    const int b     = blockIdx.z;
    const float* xb = x + (size_t)b * EDIM * N_TOK;

    float c[2][8][4];
#pragma unroll
    for (int i = 0; i < 2; i++)
#pragma unroll
        for (int j = 0; j < 8; j++)
#pragma unroll
            for (int q = 0; q < 4; q++) c[i][j][q] = 0.f;

    const int at_row = (lane >> 4) * 8 + (lane & 7);        // A-trans: e-offset
    const int at_col = ((lane >> 3) & 1) * 8;               // A-trans: m-offset
    const int bk_row = wf * 64 + ((lane >> 4) & 1) * 8 + (lane & 7);  // B: f-row
    const int bk_col = ((lane >> 3) & 1) * 8;               // B: e-offset

    for (int e0 = 0; e0 < EDIM; e0 += 64) {
        __syncthreads();
        // Xs[e][m]: 64 x 128, coalesced along m
#pragma unroll
        for (int i = 0; i < 8; i++) {
            int lin = tid + i * 256;
            int e = lin >> 5, m4 = (lin & 31) * 4;
            float4 v = *(const float4*)(xb + (size_t)(e0 + e) * N_TOK + mbase + m4);
            uint32_t p0 = bf2pack(v.x, v.y), p1 = bf2pack(v.z, v.w);
            *(uint2*)(&Xs[e][m4]) = make_uint2(p0, p1);
        }
        // Ws[f][e]: 128 x 64
#pragma unroll
        for (int i = 0; i < 8; i++) {
            int lin = tid + i * 256;
            int f = lin >> 4, e4 = (lin & 15) * 4;
            float4 v = *(const float4*)(w + (size_t)(fbase + f) * EDIM + e0 + e4);
            uint32_t p0 = bf2pack(v.x, v.y), p1 = bf2pack(v.z, v.w);
            *(uint2*)(&Ws[f][e4]) = make_uint2(p0, p1);
        }
        __syncthreads();

#pragma unroll
        for (int ks = 0; ks < 4; ks++) {
            uint32_t a[2][4];
#pragma unroll
            for (int mi = 0; mi < 2; mi++)
                ldsm_x4_t(a[mi][0], a[mi][1], a[mi][2], a[mi][3],
                          sptr(&Xs[ks * 16 + at_row][wm * 32 + mi * 16 + at_col]));
#pragma unroll
            for (int p = 0; p < 4; p++) {
                uint32_t b0, b1, b2, b3;
                ldsm_x4(b0, b1, b2, b3, sptr(&Ws[bk_row + p * 16][ks * 16 + bk_col]));
#pragma unroll
                for (int mi = 0; mi < 2; mi++) {
                    mma_bf16(c[mi][2 * p],     a[mi][0], a[mi][1], a[mi][2], a[mi][3], b0, b1);
                    mma_bf16(c[mi][2 * p + 1], a[mi][0], a[mi][1], a[mi][2], a[mi][3], b2, b3);
                }
            }
        }
    }

    // epilogue: + bias, bf16 pack, store [m][f]
#pragma unroll
    for (int ni = 0; ni < 8; ni++) {
        int f = fbase + wf * 64 + ni * 8 + 2 * t;
        float2 bb = *(const float2*)(bias + f);
#pragma unroll
        for (int mi = 0; mi < 2; mi++) {
            int m0 = mbase + wm * 32 + mi * 16 + g;
            uint32_t ptop = bf2pack(c[mi][ni][0] + bb.x, c[mi][ni][1] + bb.y);
            uint32_t pbot = bf2pack(c[mi][ni][2] + bb.x, c[mi][ni][3] + bb.y);
            *(uint32_t*)(&g_qkvh[((size_t)b * N_TOK + m0) * F3 + f])     = ptop;
            *(uint32_t*)(&g_qkvh[((size_t)b * N_TOK + m0 + 8) * F3 + f]) = pbot;
        }
    }
}

// ---------------------------------------------------------------------------
// Kernel 2: flash attention. 128 q rows / CTA, 512 threads (16 warps),
// cp.async prefetch, fragment softmax. 1 CTA/SM, grid = one wave.
// S phase : warp (rt=w&7, half=w>>3): 16 rows x 32 k-cols.
// PV phase: warp (rt2=w&3, dq=w>>2): 32 rows x 64 d-cols.
// ---------------------------------------------------------------------------
#define QS_STRIDE 264   // bf16, 528B row, %128 == 16 -> conflict-free ldsm
#define QROWS 128

struct AttnSmem {
    __nv_bfloat16 Qs[QROWS][QS_STRIDE];
    __nv_bfloat16 Ks[64][QS_STRIDE];
    __nv_bfloat16 Vs[64][QS_STRIDE];
    __nv_bfloat16 Ps[QROWS][KS_STRIDE];
    float Mred[QROWS][2];
    float Lred[QROWS][2];
    float m_s[QROWS], l_s[QROWS], scr[QROWS];
};

__global__ __launch_bounds__(512, 1) void attn_kernel() {
    extern __shared__ char smem_raw[];
    AttnSmem& S = *reinterpret_cast<AttnSmem*>(smem_raw);

    const int tid  = threadIdx.x;
    const int lane = tid & 31;
    const int w    = tid >> 5;
    const int g    = lane >> 2;
    const int t    = lane & 3;
    const int rt16 = (w & 7) * 16;      // S-phase row tile (8 tiles x 16 rows)
    const int half = w >> 3;            // S-phase k half
    const int rt2  = w & 3;             // PV row group (4 groups x 32 rows)
    const int dq   = w >> 2;            // PV d quarter (4 quarters x 64 cols)
    const int qbase = blockIdx.x * QROWS;
    const int b     = blockIdx.y;
    const __nv_bfloat16* qkv = g_qkvh + (size_t)b * N_TOK * F3;

    const int top = rt16 + g, bot = rt16 + g + 8;

    // ---- prologue: issue K_0 (2048 chunks / 512 thr = 4 each) ----
#pragma unroll
    for (int i = 0; i < 4; i++) {
        int c = tid + i * 512;
        int row = c >> 5, col = (c & 31) * 8;
        cp16(sptr(&S.Ks[row][col]), qkv + (size_t)row * F3 + 256 + col);
    }
    CP_COMMIT();

    // ---- load Q tile [128][256] (4096 chunks / 512 thr = 8 each) ----
    {
        const int ldrow = tid >> 2, ldq4 = tid & 3;   // 128 rows x 4 thr/row
#pragma unroll
        for (int i = 0; i < 8; i++) {
            int col = ldq4 * 64 + i * 8;
            uint4 v = *(const uint4*)(qkv + (size_t)(qbase + ldrow) * F3 + col);
            *(uint4*)(&S.Qs[ldrow][col]) = v;
        }
    }
    if (tid < QROWS) { S.m_s[tid] = -INFINITY; S.l_s[tid] = 0.f; }

    float cO[2][8][4];
#pragma unroll
    for (int mi = 0; mi < 2; mi++)
#pragma unroll
        for (int i = 0; i < 8; i++)
#pragma unroll
            for (int j = 0; j < 4; j++) cO[mi][i][j] = 0.f;

    // S-phase addresses
    const int a_row   = rt16 + (lane & 15);
    const int a_coff  = (lane >> 4) * 8;
    const int bk_row  = half * 32 + ((lane >> 4) & 1) * 8 + (lane & 7);
    const int bk_coff = ((lane >> 3) & 1) * 8;
    // PV addresses
    const int pv_arow = rt2 * 32 + (lane & 15);
    const int bv_krow = ((lane >> 3) & 1) * 8 + (lane & 7);
    const int bv_doff = (lane >> 4) * 8;

    for (int kb = 0; kb < N_TOK; kb += 64) {
        // ---- entry: K_i ready; V buffer free ----
        CP_WAIT(0);
        __syncthreads();

        // issue V_i (overlaps S + softmax)
#pragma unroll
        for (int i = 0; i < 4; i++) {
            int c = tid + i * 512;
            int row = c >> 5, col = (c & 31) * 8;
            cp16(sptr(&S.Vs[row][col]), qkv + (size_t)(kb + row) * F3 + 512 + col);
        }
        CP_COMMIT();

        // ---- S = Q K^T (warp: 16 rows x 32 cols), no internal syncs ----
        float cS[4][4];
#pragma unroll
        for (int n = 0; n < 4; n++)
#pragma unroll
            for (int j = 0; j < 4; j++) cS[n][j] = 0.f;

#pragma unroll
        for (int dc = 0; dc < 4; dc++) {
#pragma unroll
            for (int ks = 0; ks < 4; ks++) {
                int d0 = dc * 64 + ks * 16;
                uint32_t a0, a1, a2, a3;
                ldsm_x4(a0, a1, a2, a3, sptr(&S.Qs[a_row][d0 + a_coff]));
#pragma unroll
                for (int p = 0; p < 2; p++) {
                    uint32_t b0, b1, b2, b3;
                    ldsm_x4(b0, b1, b2, b3, sptr(&S.Ks[bk_row + p * 16][d0 + bk_coff]));
                    mma_bf16(cS[2 * p],     a0, a1, a2, a3, b0, b1);
                    mma_bf16(cS[2 * p + 1], a0, a1, a2, a3, b2, b3);
                }
            }
        }

        __syncthreads();   // S done everywhere -> K buffer free

        // issue K_{i+1} (overlaps softmax + PV); wrap harmlessly on last tile
        {
            int kb2 = (kb + 64) & (N_TOK - 1);
#pragma unroll
            for (int i = 0; i < 4; i++) {
                int c = tid + i * 512;
                int row = c >> 5, col = (c & 31) * 8;
                cp16(sptr(&S.Ks[row][col]), qkv + (size_t)(kb2 + row) * F3 + 256 + col);
            }
            CP_COMMIT();
        }

        // ---- softmax on fragments ----
        float mt = -INFINITY, mb = -INFINITY;
#pragma unroll
        for (int nt = 0; nt < 4; nt++) {
            cS[nt][0] *= SCL; cS[nt][1] *= SCL; cS[nt][2] *= SCL; cS[nt][3] *= SCL;
            mt = fmaxf(mt, fmaxf(cS[nt][0], cS[nt][1]));
            mb = fmaxf(mb, fmaxf(cS[nt][2], cS[nt][3]));
        }
        mt = fmaxf(mt, __shfl_xor_sync(0xffffffffu, mt, 1));
        mt = fmaxf(mt, __shfl_xor_sync(0xffffffffu, mt, 2));
        mb = fmaxf(mb, __shfl_xor_sync(0xffffffffu, mb, 1));
        mb = fmaxf(mb, __shfl_xor_sync(0xffffffffu, mb, 2));
        if (t == 0) { S.Mred[top][half] = mt; S.Mred[bot][half] = mb; }
        __syncthreads();   // Mred ready

        float mwt = fmaxf(S.Mred[top][0], S.Mred[top][1]);
        float mwb = fmaxf(S.Mred[bot][0], S.Mred[bot][1]);
        float moldt = S.m_s[top], moldb = S.m_s[bot];
        float mnt = fmaxf(moldt, mwt), mnb = fmaxf(moldb, mwb);
        float sct = __expf(moldt - mnt), scb = __expf(moldb - mnb);
        float st = 0.f, sb = 0.f;
#pragma unroll
        for (int nt = 0; nt < 4; nt++) {
            float e0 = __expf(cS[nt][0] - mnt), e1 = __expf(cS[nt][1] - mnt);
            float e2 = __expf(cS[nt][2] - mnb), e3 = __expf(cS[nt][3] - mnb);
            int col = half * 32 + nt * 8 + 2 * t;
            *(uint32_t*)(&S.Ps[top][col]) = bf2pack(e0, e1);
            *(uint32_t*)(&S.Ps[bot][col]) = bf2pack(e2, e3);
            st += e0 + e1; sb += e2 + e3;
        }
        st += __shfl_xor_sync(0xffffffffu, st, 1);
        st += __shfl_xor_sync(0xffffffffu, st, 2);
        sb += __shfl_xor_sync(0xffffffffu, sb, 1);
        sb += __shfl_xor_sync(0xffffffffu, sb, 2);
        if (t == 0) {
            S.Lred[top][half] = st; S.Lred[bot][half] = sb;
            S.scr[top] = sct;       S.scr[bot] = scb;     // same value both halves
        }

        CP_WAIT(1);        // V_i done (K_{i+1} may still be in flight)
        __syncthreads();   // Ps/Lred/scr ready + V visible

        if (half == 0 && t == 0) {
            S.m_s[top] = mnt;
            S.l_s[top] = S.l_s[top] * sct + S.Lred[top][0] + S.Lred[top][1];
            S.m_s[bot] = mnb;
            S.l_s[bot] = S.l_s[bot] * scb + S.Lred[bot][0] + S.Lred[bot][1];
        }

        // ---- PV: warp = 32 rows (rt2) x 64 d (dq) ----
        {
            float s00 = S.scr[rt2 * 32 + g],      s01 = S.scr[rt2 * 32 + g + 8];
            float s10 = S.scr[rt2 * 32 + 16 + g], s11 = S.scr[rt2 * 32 + 16 + g + 8];
#pragma unroll
            for (int ni = 0; ni < 8; ni++) {
                cO[0][ni][0] *= s00; cO[0][ni][1] *= s00;
                cO[0][ni][2] *= s01; cO[0][ni][3] *= s01;
                cO[1][ni][0] *= s10; cO[1][ni][1] *= s10;
                cO[1][ni][2] *= s11; cO[1][ni][3] *= s11;
            }
        }
#pragma unroll
        for (int ks = 0; ks < 4; ks++) {
            uint32_t a[2][4];
#pragma unroll
            for (int mi = 0; mi < 2; mi++)
                ldsm_x4(a[mi][0], a[mi][1], a[mi][2], a[mi][3],
                        sptr(&S.Ps[pv_arow + mi * 16][ks * 16 + a_coff]));
#pragma unroll
            for (int p = 0; p < 4; p++) {
                uint32_t b0, b1, b2, b3;
                ldsm_x4_t(b0, b1, b2, b3,
                          sptr(&S.Vs[ks * 16 + bv_krow][dq * 64 + p * 16 + bv_doff]));
#pragma unroll
                for (int mi = 0; mi < 2; mi++) {
                    mma_bf16(cO[mi][2 * p],     a[mi][0], a[mi][1], a[mi][2], a[mi][3], b0, b1);
                    mma_bf16(cO[mi][2 * p + 1], a[mi][0], a[mi][1], a[mi][2], a[mi][3], b2, b3);
                }
            }
        }
    }

    __syncthreads();   // final l_s update visible

    // ---- normalize + write bf16 ----
    {
        size_t bN = (size_t)b * N_TOK;
#pragma unroll
        for (int mi = 0; mi < 2; mi++) {
            int r0 = rt2 * 32 + mi * 16 + g;
            float inv0 = 1.f / S.l_s[r0];
            float inv1 = 1.f / S.l_s[r0 + 8];
            size_t row0 = (bN + qbase + r0) * EDIM;
            size_t row1 = (bN + qbase + r0 + 8) * EDIM;
#pragma unroll
            for (int ni = 0; ni < 8; ni++) {
                int col = dq * 64 + ni * 8 + 2 * t;
                *(uint32_t*)(&g_obh[row0 + col]) =
                    bf2pack(cO[mi][ni][0] * inv0, cO[mi][ni][1] * inv0);
                *(uint32_t*)(&g_obh[row1 + col]) =
                    bf2pack(cO[mi][ni][2] * inv1, cO[mi][ni][3] * inv1);
            }
        }
    }
}

// ---------------------------------------------------------------------------
// Kernel 3: out[b, e, m] = x + sum_k out_w[e,k] * o[m,k] + out_b[e]  (bf16 mma)
// CTA: 128 e x 128 m, k-chunk 64. Warps 4(e) x 2(m), warp tile 32e x 64m.
// ---------------------------------------------------------------------------
__global__ __launch_bounds__(256, 2) void out_kernel(const float* __restrict__ x,
                                                     const float* __restrict__ w,
                                                     const float* __restrict__ bias,
                                                     float* __restrict__ out) {
    __shared__ __nv_bfloat16 Ws2[128][KS_STRIDE];  // [e][k]
    __shared__ __nv_bfloat16 Os[128][KS_STRIDE];   // [m][k]
    const int tid  = threadIdx.x;
    const int lane = tid & 31;
    const int wp   = tid >> 5;
    const int g    = lane >> 2;
    const int t    = lane & 3;
    const int we   = wp >> 1;           // 0..3 : e-subtile of 32
    const int wm   = wp & 1;            // 0..1 : m-subtile of 64
    const int mbase = blockIdx.x * 128;
    const int ebase = blockIdx.y * 128;
    const int b     = blockIdx.z;

    float c[2][8][4];
#pragma unroll
    for (int i = 0; i < 2; i++)
#pragma unroll
        for (int j = 0; j < 8; j++)
#pragma unroll
            for (int q = 0; q < 4; q++) c[i][j][q] = 0.f;

    const int a_row  = we * 32 + (lane & 15);
    const int a_coff = (lane >> 4) * 8;
    const int b_row  = wm * 64 + ((lane >> 4) & 1) * 8 + (lane & 7);
    const int b_coff = ((lane >> 3) & 1) * 8;

    for (int k0 = 0; k0 < EDIM; k0 += 64) {
        __syncthreads();
        // Ws2[e][k]: 128 x 64 fp32 -> bf16
#pragma unroll
        for (int i = 0; i < 8; i++) {
            int lin = tid + i * 256;
            int e = lin >> 4, k4 = (lin & 15) * 4;
            float4 v = *(const float4*)(w + (size_t)(ebase + e) * EDIM + k0 + k4);
            uint32_t p0 = bf2pack(v.x, v.y), p1 = bf2pack(v.z, v.w);
            *(uint2*)(&Ws2[e][k4]) = make_uint2(p0, p1);
        }
        // Os[m][k]: 128 x 64 bf16
#pragma unroll
        for (int i = 0; i < 4; i++) {
            int lin = tid + i * 256;
            int m = lin >> 3, k8 = (lin & 7) * 8;
            uint4 v = *(const uint4*)(g_obh + ((size_t)b * N_TOK + mbase + m) * EDIM + k0 + k8);
            *(uint4*)(&Os[m][k8]) = v;
        }
        __syncthreads();

#pragma unroll
        for (int ks = 0; ks < 4; ks++) {
            uint32_t a[2][4];
#pragma unroll
            for (int mi = 0; mi < 2; mi++)
                ldsm_x4(a[mi][0], a[mi][1], a[mi][2], a[mi][3],
                        sptr(&Ws2[a_row + mi * 16][ks * 16 + a_coff]));
#pragma unroll
            for (int p = 0; p < 4; p++) {
                uint32_t b0, b1, b2, b3;
                ldsm_x4(b0, b1, b2, b3, sptr(&Os[b_row + p * 16][ks * 16 + b_coff]));
#pragma unroll
                for (int mi = 0; mi < 2; mi++) {
                    mma_bf16(c[mi][2 * p],     a[mi][0], a[mi][1], a[mi][2], a[mi][3], b0, b1);
                    mma_bf16(c[mi][2 * p + 1], a[mi][0], a[mi][1], a[mi][2], a[mi][3], b2, b3);
                }
            }
        }
    }

    // epilogue: residual + bias, fp32 out [e][m]
#pragma unroll
    for (int mi = 0; mi < 2; mi++) {
        int e0 = ebase + we * 32 + mi * 16 + g;
        float bt = bias[e0], bb = bias[e0 + 8];
#pragma unroll
        for (int ni = 0; ni < 8; ni++) {
            int m = mbase + wm * 64 + ni * 8 + 2 * t;
            size_t it = ((size_t)b * EDIM + e0) * N_TOK + m;
            size_t ib = ((size_t)b * EDIM + e0 + 8) * N_TOK + m;
            float2 xt = *(const float2*)(x + it);
            float2 xb = *(const float2*)(x + ib);
            *(float2*)(out + it) = make_float2(xt.x + c[mi][ni][0] + bt,
                                               xt.y + c[mi][ni][1] + bt);
            *(float2*)(out + ib) = make_float2(xb.x + c[mi][ni][2] + bb,
                                               xb.y + c[mi][ni][3] + bb);
        }
    }
}

// ---------------------------------------------------------------------------
extern "C" void kernel_launch(void* const* d_in, const int* in_sizes, int n_in,
                              void* d_out, int out_size) {
    const float* x = nullptr; const float* qkv_w = nullptr; const float* qkv_b = nullptr;
    const float* out_w = nullptr; const float* out_b = nullptr;
    for (int i = 0; i < n_in; i++) {
        switch (in_sizes[i]) {
            case 4194304: x     = (const float*)d_in[i]; break;
            case  196608: qkv_w = (const float*)d_in[i]; break;
            case     768: qkv_b = (const float*)d_in[i]; break;
            case   65536: out_w = (const float*)d_in[i]; break;
            case     256: out_b = (const float*)d_in[i]; break;
            default: break;
        }
    }
    float* out = (float*)d_out;

    cudaFuncSetAttribute(attn_kernel, cudaFuncAttributeMaxDynamicSharedMemorySize,
                         (int)sizeof(AttnSmem));

    qkv_kernel<<<dim3(N_TOK / 128, F3 / 128, B_SZ), 256>>>(x, qkv_w, qkv_b);
    attn_kernel<<<dim3(N_TOK / QROWS, B_SZ), 512, sizeof(AttnSmem)>>>();
    out_kernel<<<dim3(N_TOK / 128, EDIM / 128, B_SZ), 256>>>(x, out_w, out_b, out);
}

// round 16
// speedup vs baseline: 8.9174x; 1.0066x over previous
#include <cuda_runtime.h>
#include <cuda_fp16.h>
#include <math.h>
#include <stdint.h>

#define B_SZ   4
#define EDIM   256
#define N_TOK  4096
#define F3     768
#define SCL    0.0625f   // 1/sqrt(256)
#define LOG2E  1.4426950408889634f

// Scratch (allocation-free rule: __device__ globals)
__device__ __align__(16) __half g_qkvh[(size_t)B_SZ * N_TOK * F3]; // [b, n, 3E]
__device__ __align__(16) __half g_obh[(size_t)B_SZ * N_TOK * EDIM]; // [b, n, E]

__device__ __forceinline__ void ldsm_x4(uint32_t& r0, uint32_t& r1, uint32_t& r2, uint32_t& r3,
                                        uint32_t addr) {
    asm volatile("ldmatrix.sync.aligned.m8n8.x4.shared.b16 {%0,%1,%2,%3}, [%4];"
                 : "=r"(r0), "=r"(r1), "=r"(r2), "=r"(r3) : "r"(addr));
}
__device__ __forceinline__ void ldsm_x4_t(uint32_t& r0, uint32_t& r1, uint32_t& r2, uint32_t& r3,
                                          uint32_t addr) {
    asm volatile("ldmatrix.sync.aligned.m8n8.x4.trans.shared.b16 {%0,%1,%2,%3}, [%4];"
                 : "=r"(r0), "=r"(r1), "=r"(r2), "=r"(r3) : "r"(addr));
}
__device__ __forceinline__ void mma_f16(float c[4], uint32_t a0, uint32_t a1, uint32_t a2,
                                        uint32_t a3, uint32_t b0, uint32_t b1) {
    asm volatile(
        "mma.sync.aligned.m16n8k16.row.col.f32.f16.f16.f32 "
        "{%0,%1,%2,%3}, {%4,%5,%6,%7}, {%8,%9}, {%0,%1,%2,%3};\n"
        : "+f"(c[0]), "+f"(c[1]), "+f"(c[2]), "+f"(c[3])
        : "r"(a0), "r"(a1), "r"(a2), "r"(a3), "r"(b0), "r"(b1));
}
__device__ __forceinline__ uint32_t sptr(const void* p) {
    return (uint32_t)__cvta_generic_to_shared(p);
}
// pack (lo, hi) floats into f16x2 (lo in low half). cvt d,a,b: a->high, b->low
__device__ __forceinline__ uint32_t h2pack(float lo, float hi) {
    uint32_t r;
    asm("cvt.rn.f16x2.f32 %0, %1, %2;" : "=r"(r) : "f"(hi), "f"(lo));
    return r;
}
// packed exp2 on two fp16 values
__device__ __forceinline__ uint32_t ex2h2(uint32_t x) {
    uint32_t r;
    asm("ex2.approx.f16x2 %0, %1;" : "=r"(r) : "r"(x));
    return r;
}
__device__ __forceinline__ float2 h22f2(uint32_t p) {
    __half2 h = *reinterpret_cast<__half2*>(&p);
    return __half22float2(h);
}
__device__ __forceinline__ void cp16(uint32_t dst, const void* src) {
    asm volatile("cp.async.cg.shared.global [%0], [%1], 16;" :: "r"(dst), "l"(src));
}
#define CP_COMMIT() asm volatile("cp.async.commit_group;")
#define CP_WAIT(n)  asm volatile("cp.async.wait_group %0;" :: "n"(n))

#define XS_STRIDE 136   // 272B % 128 == 16 -> conflict-free ldsm
#define KS_STRIDE 72    // 144B % 128 == 16

// ---------------------------------------------------------------------------
// Kernel 1: qkv[b, m, f] = sum_e x[b, e, m] * w[f, e] + bias[f]   (f16 mma)
// CTA: 128 m x 128 f, k-chunk 64. Warps 4(m) x 2(f), warp tile 32m x 64f.
// ---------------------------------------------------------------------------
__global__ __launch_bounds__(256, 2) void qkv_kernel(const float* __restrict__ x,
                                                     const float* __restrict__ w,
                                                     const float* __restrict__ bias) {
    __shared__ __half Xs[64][XS_STRIDE];    // [e][m]
    __shared__ __half Ws[128][KS_STRIDE];   // [f][e]
    const int tid  = threadIdx.x;
    const int lane = tid & 31;
    const int wp   = tid >> 5;
    const int g    = lane >> 2;
    const int t    = lane & 3;
    const int wm   = wp >> 1;
    const int wf   = wp & 1;
    const int mbase = blockIdx.x * 128;
    const int fbase = blockIdx.y * 128;
    const int b     = blockIdx.z;
    const float* xb = x + (size_t)b * EDIM * N_TOK;

    float c[2][8][4];
#pragma unroll
    for (int i = 0; i < 2; i++)
#pragma unroll
        for (int j = 0; j < 8; j++)
#pragma unroll
            for (int q = 0; q < 4; q++) c[i][j][q] = 0.f;

    const int at_row = (lane >> 4) * 8 + (lane & 7);
    const int at_col = ((lane >> 3) & 1) * 8;
    const int bk_row = wf * 64 + ((lane >> 4) & 1) * 8 + (lane & 7);
    const int bk_col = ((lane >> 3) & 1) * 8;

    for (int e0 = 0; e0 < EDIM; e0 += 64) {
        __syncthreads();
#pragma unroll
        for (int i = 0; i < 8; i++) {
            int lin = tid + i * 256;
            int e = lin >> 5, m4 = (lin & 31) * 4;
            float4 v = *(const float4*)(xb + (size_t)(e0 + e) * N_TOK + mbase + m4);
            uint32_t p0 = h2pack(v.x, v.y), p1 = h2pack(v.z, v.w);
            *(uint2*)(&Xs[e][m4]) = make_uint2(p0, p1);
        }
#pragma unroll
        for (int i = 0; i < 8; i++) {
            int lin = tid + i * 256;
            int f = lin >> 4, e4 = (lin & 15) * 4;
            float4 v = *(const float4*)(w + (size_t)(fbase + f) * EDIM + e0 + e4);
            uint32_t p0 = h2pack(v.x, v.y), p1 = h2pack(v.z, v.w);
            *(uint2*)(&Ws[f][e4]) = make_uint2(p0, p1);
        }
        __syncthreads();

#pragma unroll
        for (int ks = 0; ks < 4; ks++) {
            uint32_t a[2][4];
#pragma unroll
            for (int mi = 0; mi < 2; mi++)
                ldsm_x4_t(a[mi][0], a[mi][1], a[mi][2], a[mi][3],
                          sptr(&Xs[ks * 16 + at_row][wm * 32 + mi * 16 + at_col]));
#pragma unroll
            for (int p = 0; p < 4; p++) {
                uint32_t b0, b1, b2, b3;
                ldsm_x4(b0, b1, b2, b3, sptr(&Ws[bk_row + p * 16][ks * 16 + bk_col]));
#pragma unroll
                for (int mi = 0; mi < 2; mi++) {
                    mma_f16(c[mi][2 * p],     a[mi][0], a[mi][1], a[mi][2], a[mi][3], b0, b1);
                    mma_f16(c[mi][2 * p + 1], a[mi][0], a[mi][1], a[mi][2], a[mi][3], b2, b3);
                }
            }
        }
    }

    // epilogue: + bias, f16 pack, store [m][f]
#pragma unroll
    for (int ni = 0; ni < 8; ni++) {
        int f = fbase + wf * 64 + ni * 8 + 2 * t;
        float2 bb = *(const float2*)(bias + f);
#pragma unroll
        for (int mi = 0; mi < 2; mi++) {
            int m0 = mbase + wm * 32 + mi * 16 + g;
            uint32_t ptop = h2pack(c[mi][ni][0] + bb.x, c[mi][ni][1] + bb.y);
            uint32_t pbot = h2pack(c[mi][ni][2] + bb.x, c[mi][ni][3] + bb.y);
            *(uint32_t*)(&g_qkvh[((size_t)b * N_TOK + m0) * F3 + f])     = ptop;
            *(uint32_t*)(&g_qkvh[((size_t)b * N_TOK + m0 + 8) * F3 + f]) = pbot;
        }
    }
}

// ---------------------------------------------------------------------------
// Kernel 2: flash attention. 128 q rows / CTA, 512 threads (16 warps),
// cp.async prefetch, fragment softmax with packed f16x2 exp2.
// S phase : warp (rt=w&7, half=w>>3): 16 rows x 32 k-cols.
// PV phase: warp (rt2=w&3, dq=w>>2): 32 rows x 64 d-cols.
// ---------------------------------------------------------------------------
#define QS_STRIDE 264   // f16, 528B row, %128 == 16 -> conflict-free ldsm
#define QROWS 128

struct AttnSmem {
    __half Qs[QROWS][QS_STRIDE];
    __half Ks[64][QS_STRIDE];
    __half Vs[64][QS_STRIDE];
    __half Ps[QROWS][KS_STRIDE];
    float Mred[QROWS][2];
    float Lred[QROWS][2];
    float m_s[QROWS], l_s[QROWS], scr[QROWS];
};

__global__ __launch_bounds__(512, 1) void attn_kernel() {
    extern __shared__ char smem_raw[];
    AttnSmem& S = *reinterpret_cast<AttnSmem*>(smem_raw);

    const int tid  = threadIdx.x;
    const int lane = tid & 31;
    const int w    = tid >> 5;
    const int g    = lane >> 2;
    const int t    = lane & 3;
    const int rt16 = (w & 7) * 16;      // S-phase row tile (8 tiles x 16 rows)
    const int half = w >> 3;            // S-phase k half
    const int rt2  = w & 3;             // PV row group (4 groups x 32 rows)
    const int dq   = w >> 2;            // PV d quarter (4 quarters x 64 cols)
    const int qbase = blockIdx.x * QROWS;
    const int b     = blockIdx.y;
    const __half* qkv = g_qkvh + (size_t)b * N_TOK * F3;

    const int top = rt16 + g, bot = rt16 + g + 8;

    // ---- prologue: issue K_0 (2048 chunks / 512 thr = 4 each) ----
#pragma unroll
    for (int i = 0; i < 4; i++) {
        int c = tid + i * 512;
        int row = c >> 5, col = (c & 31) * 8;
        cp16(sptr(&S.Ks[row][col]), qkv + (size_t)row * F3 + 256 + col);
    }
    CP_COMMIT();

    // ---- load Q tile [128][256] ----
    {
        const int ldrow = tid >> 2, ldq4 = tid & 3;
#pragma unroll
        for (int i = 0; i < 8; i++) {
            int col = ldq4 * 64 + i * 8;
            uint4 v = *(const uint4*)(qkv + (size_t)(qbase + ldrow) * F3 + col);
            *(uint4*)(&S.Qs[ldrow][col]) = v;
        }
    }
    if (tid < QROWS) { S.m_s[tid] = -INFINITY; S.l_s[tid] = 0.f; }

    float cO[2][8][4];
#pragma unroll
    for (int mi = 0; mi < 2; mi++)
#pragma unroll
        for (int i = 0; i < 8; i++)
#pragma unroll
            for (int j = 0; j < 4; j++) cO[mi][i][j] = 0.f;

    // S-phase addresses
    const int a_row   = rt16 + (lane & 15);
    const int a_coff  = (lane >> 4) * 8;
    const int bk_row  = half * 32 + ((lane >> 4) & 1) * 8 + (lane & 7);
    const int bk_coff = ((lane >> 3) & 1) * 8;
    // PV addresses
    const int pv_arow = rt2 * 32 + (lane & 15);
    const int bv_krow = ((lane >> 3) & 1) * 8 + (lane & 7);
    const int bv_doff = (lane >> 4) * 8;

    for (int kb = 0; kb < N_TOK; kb += 64) {
        // ---- entry: K_i ready; V buffer free ----
        CP_WAIT(0);
        __syncthreads();

        // issue V_i (overlaps S + softmax)
#pragma unroll
        for (int i = 0; i < 4; i++) {
            int c = tid + i * 512;
            int row = c >> 5, col = (c & 31) * 8;
            cp16(sptr(&S.Vs[row][col]), qkv + (size_t)(kb + row) * F3 + 512 + col);
        }
        CP_COMMIT();

        // ---- S = Q K^T (warp: 16 rows x 32 cols), no internal syncs ----
        float cS[4][4];
#pragma unroll
        for (int n = 0; n < 4; n++)
#pragma unroll
            for (int j = 0; j < 4; j++) cS[n][j] = 0.f;

#pragma unroll
        for (int dc = 0; dc < 4; dc++) {
#pragma unroll
            for (int ks = 0; ks < 4; ks++) {
                int d0 = dc * 64 + ks * 16;
                uint32_t a0, a1, a2, a3;
                ldsm_x4(a0, a1, a2, a3, sptr(&S.Qs[a_row][d0 + a_coff]));
#pragma unroll
                for (int p = 0; p < 2; p++) {
                    uint32_t b0, b1, b2, b3;
                    ldsm_x4(b0, b1, b2, b3, sptr(&S.Ks[bk_row + p * 16][d0 + bk_coff]));
                    mma_f16(cS[2 * p],     a0, a1, a2, a3, b0, b1);
                    mma_f16(cS[2 * p + 1], a0, a1, a2, a3, b2, b3);
                }
            }
        }

        __syncthreads();   // S done everywhere -> K buffer free

        // issue K_{i+1} (overlaps softmax + PV); wrap harmlessly on last tile
        {
            int kb2 = (kb + 64) & (N_TOK - 1);
#pragma unroll
            for (int i = 0; i < 4; i++) {
                int c = tid + i * 512;
                int row = c >> 5, col = (c & 31) * 8;
                cp16(sptr(&S.Ks[row][col]), qkv + (size_t)(kb2 + row) * F3 + 256 + col);
            }
            CP_COMMIT();
        }

        // ---- softmax on fragments (packed f16x2 exp2) ----
        float mt = -INFINITY, mb = -INFINITY;
#pragma unroll
        for (int nt = 0; nt < 4; nt++) {
            cS[nt][0] *= SCL; cS[nt][1] *= SCL; cS[nt][2] *= SCL; cS[nt][3] *= SCL;
            mt = fmaxf(mt, fmaxf(cS[nt][0], cS[nt][1]));
            mb = fmaxf(mb, fmaxf(cS[nt][2], cS[nt][3]));
        }
        mt = fmaxf(mt, __shfl_xor_sync(0xffffffffu, mt, 1));
        mt = fmaxf(mt, __shfl_xor_sync(0xffffffffu, mt, 2));
        mb = fmaxf(mb, __shfl_xor_sync(0xffffffffu, mb, 1));
        mb = fmaxf(mb, __shfl_xor_sync(0xffffffffu, mb, 2));
        if (t == 0) { S.Mred[top][half] = mt; S.Mred[bot][half] = mb; }
        __syncthreads();   // Mred ready

        float mwt = fmaxf(S.Mred[top][0], S.Mred[top][1]);
        float mwb = fmaxf(S.Mred[bot][0], S.Mred[bot][1]);
        float moldt = S.m_s[top], moldb = S.m_s[bot];
        float mnt = fmaxf(moldt, mwt), mnb = fmaxf(moldb, mwb);
        float sct = __expf(moldt - mnt), scb = __expf(moldb - mnb);
        float mlt = mnt * LOG2E, mlb = mnb * LOG2E;   // exp(x-m)=2^(x*log2e - m*log2e)
        float st = 0.f, sb = 0.f;
#pragma unroll
        for (int nt = 0; nt < 4; nt++) {
            int col = half * 32 + nt * 8 + 2 * t;
            // top row pair
            float a0 = fmaf(cS[nt][0], LOG2E, -mlt);
            float a1 = fmaf(cS[nt][1], LOG2E, -mlt);
            uint32_t pt = ex2h2(h2pack(a0, a1));
            *(uint32_t*)(&S.Ps[top][col]) = pt;
            float2 ft = h22f2(pt);
            st += ft.x + ft.y;
            // bottom row pair
            float a2 = fmaf(cS[nt][2], LOG2E, -mlb);
            float a3 = fmaf(cS[nt][3], LOG2E, -mlb);
            uint32_t pb = ex2h2(h2pack(a2, a3));
            *(uint32_t*)(&S.Ps[bot][col]) = pb;
            float2 fb = h22f2(pb);
            sb += fb.x + fb.y;
        }
        st += __shfl_xor_sync(0xffffffffu, st, 1);
        st += __shfl_xor_sync(0xffffffffu, st, 2);
        sb += __shfl_xor_sync(0xffffffffu, sb, 1);
        sb += __shfl_xor_sync(0xffffffffu, sb, 2);
        if (t == 0) {
            S.Lred[top][half] = st; S.Lred[bot][half] = sb;
            S.scr[top] = sct;       S.scr[bot] = scb;     // same value both halves
        }

        CP_WAIT(1);        // V_i done (K_{i+1} may still be in flight)
        __syncthreads();   // Ps/Lred/scr ready + V visible

        if (half == 0 && t == 0) {
            S.m_s[top] = mnt;
            S.l_s[top] = S.l_s[top] * sct + S.Lred[top][0] + S.Lred[top][1];
            S.m_s[bot] = mnb;
            S.l_s[bot] = S.l_s[bot] * scb + S.Lred[bot][0] + S.Lred[bot][1];
        }

        // ---- PV: warp = 32 rows (rt2) x 64 d (dq) ----
        {
            float s00 = S.scr[rt2 * 32 + g],      s01 = S.scr[rt2 * 32 + g + 8];
            float s10 = S.scr[rt2 * 32 + 16 + g], s11 = S.scr[rt2 * 32 + 16 + g + 8];
#pragma unroll
            for (int ni = 0; ni < 8; ni++) {
                cO[0][ni][0] *= s00; cO[0][ni][1] *= s00;
                cO[0][ni][2] *= s01; cO[0][ni][3] *= s01;
                cO[1][ni][0] *= s10; cO[1][ni][1] *= s10;
                cO[1][ni][2] *= s11; cO[1][ni][3] *= s11;
            }
        }
#pragma unroll
        for (int ks = 0; ks < 4; ks++) {
            uint32_t a[2][4];
#pragma unroll
            for (int mi = 0; mi < 2; mi++)
                ldsm_x4(a[mi][0], a[mi][1], a[mi][2], a[mi][3],
                        sptr(&S.Ps[pv_arow + mi * 16][ks * 16 + a_coff]));
#pragma unroll
            for (int p = 0; p < 4; p++) {
                uint32_t b0, b1, b2, b3;
                ldsm_x4_t(b0, b1, b2, b3,
                          sptr(&S.Vs[ks * 16 + bv_krow][dq * 64 + p * 16 + bv_doff]));
#pragma unroll
                for (int mi = 0; mi < 2; mi++) {
                    mma_f16(cO[mi][2 * p],     a[mi][0], a[mi][1], a[mi][2], a[mi][3], b0, b1);
                    mma_f16(cO[mi][2 * p + 1], a[mi][0], a[mi][1], a[mi][2], a[mi][3], b2, b3);
                }
            }
        }
    }

    __syncthreads();   // final l_s update visible

    // ---- normalize + write f16 ----
    {
        size_t bN = (size_t)b * N_TOK;
#pragma unroll
        for (int mi = 0; mi < 2; mi++) {
            int r0 = rt2 * 32 + mi * 16 + g;
            float inv0 = 1.f / S.l_s[r0];
            float inv1 = 1.f / S.l_s[r0 + 8];
            size_t row0 = (bN + qbase + r0) * EDIM;
            size_t row1 = (bN + qbase + r0 + 8) * EDIM;
#pragma unroll
            for (int ni = 0; ni < 8; ni++) {
                int col = dq * 64 + ni * 8 + 2 * t;
                *(uint32_t*)(&g_obh[row0 + col]) =
                    h2pack(cO[mi][ni][0] * inv0, cO[mi][ni][1] * inv0);
                *(uint32_t*)(&g_obh[row1 + col]) =
                    h2pack(cO[mi][ni][2] * inv1, cO[mi][ni][3] * inv1);
            }
        }
    }
}

// ---------------------------------------------------------------------------
// Kernel 3: out[b, e, m] = x + sum_k out_w[e,k] * o[m,k] + out_b[e]  (f16 mma)
// CTA: 128 e x 128 m, k-chunk 64. Warps 4(e) x 2(m), warp tile 32e x 64m.
// ---------------------------------------------------------------------------
__global__ __launch_bounds__(256, 2) void out_kernel(const float* __restrict__ x,
                                                     const float* __restrict__ w,
                                                     const float* __restrict__ bias,
                                                     float* __restrict__ out) {
    __shared__ __half Ws2[128][KS_STRIDE];  // [e][k]
    __shared__ __half Os[128][KS_STRIDE];   // [m][k]
    const int tid  = threadIdx.x;
    const int lane = tid & 31;
    const int wp   = tid >> 5;
    const int g    = lane >> 2;
    const int t    = lane & 3;
    const int we   = wp >> 1;
    const int wm   = wp & 1;
    const int mbase = blockIdx.x * 128;
    const int ebase = blockIdx.y * 128;
    const int b     = blockIdx.z;

    float c[2][8][4];
#pragma unroll
    for (int i = 0; i < 2; i++)
#pragma unroll
        for (int j = 0; j < 8; j++)
#pragma unroll
            for (int q = 0; q < 4; q++) c[i][j][q] = 0.f;

    const int a_row  = we * 32 + (lane & 15);
    const int a_coff = (lane >> 4) * 8;
    const int b_row  = wm * 64 + ((lane >> 4) & 1) * 8 + (lane & 7);
    const int b_coff = ((lane >> 3) & 1) * 8;

    for (int k0 = 0; k0 < EDIM; k0 += 64) {
        __syncthreads();
#pragma unroll
        for (int i = 0; i < 8; i++) {
            int lin = tid + i * 256;
            int e = lin >> 4, k4 = (lin & 15) * 4;
            float4 v = *(const float4*)(w + (size_t)(ebase + e) * EDIM + k0 + k4);
            uint32_t p0 = h2pack(v.x, v.y), p1 = h2pack(v.z, v.w);
            *(uint2*)(&Ws2[e][k4]) = make_uint2(p0, p1);
        }
#pragma unroll
        for (int i = 0; i < 4; i++) {
            int lin = tid + i * 256;
            int m = lin >> 3, k8 = (lin & 7) * 8;
            uint4 v = *(const uint4*)(g_obh + ((size_t)b * N_TOK + mbase + m) * EDIM + k0 + k8);
            *(uint4*)(&Os[m][k8]) = v;
        }
        __syncthreads();

#pragma unroll
        for (int ks = 0; ks < 4; ks++) {
            uint32_t a[2][4];
#pragma unroll
            for (int mi = 0; mi < 2; mi++)
                ldsm_x4(a[mi][0], a[mi][1], a[mi][2], a[mi][3],
                        sptr(&Ws2[a_row + mi * 16][ks * 16 + a_coff]));
#pragma unroll
            for (int p = 0; p < 4; p++) {
                uint32_t b0, b1, b2, b3;
                ldsm_x4(b0, b1, b2, b3, sptr(&Os[b_row + p * 16][ks * 16 + b_coff]));
#pragma unroll
                for (int mi = 0; mi < 2; mi++) {
                    mma_f16(c[mi][2 * p],     a[mi][0], a[mi][1], a[mi][2], a[mi][3], b0, b1);
                    mma_f16(c[mi][2 * p + 1], a[mi][0], a[mi][1], a[mi][2], a[mi][3], b2, b3);
                }
            }
        }
    }

    // epilogue: residual + bias, fp32 out [e][m]
#pragma unroll
    for (int mi = 0; mi < 2; mi++) {
        int e0 = ebase + we * 32 + mi * 16 + g;
        float bt = bias[e0], bb = bias[e0 + 8];
#pragma unroll
        for (int ni = 0; ni < 8; ni++) {
            int m = mbase + wm * 64 + ni * 8 + 2 * t;
            size_t it = ((size_t)b * EDIM + e0) * N_TOK + m;
            size_t ib = ((size_t)b * EDIM + e0 + 8) * N_TOK + m;
            float2 xt = *(const float2*)(x + it);
            float2 xb = *(const float2*)(x + ib);
            *(float2*)(out + it) = make_float2(xt.x + c[mi][ni][0] + bt,
                                               xt.y + c[mi][ni][1] + bt);
            *(float2*)(out + ib) = make_float2(xb.x + c[mi][ni][2] + bb,
                                               xb.y + c[mi][ni][3] + bb);
        }
    }
}

// ---------------------------------------------------------------------------
extern "C" void kernel_launch(void* const* d_in, const int* in_sizes, int n_in,
                              void* d_out, int out_size) {
    const float* x = nullptr; const float* qkv_w = nullptr; const float* qkv_b = nullptr;
    const float* out_w = nullptr; const float* out_b = nullptr;
    for (int i = 0; i < n_in; i++) {
        switch (in_sizes[i]) {
            case 4194304: x     = (const float*)d_in[i]; break;
            case  196608: qkv_w = (const float*)d_in[i]; break;
            case     768: qkv_b = (const float*)d_in[i]; break;
            case   65536: out_w = (const float*)d_in[i]; break;
            case     256: out_b = (const float*)d_in[i]; break;
            default: break;
        }
    }
    float* out = (float*)d_out;

    cudaFuncSetAttribute(attn_kernel, cudaFuncAttributeMaxDynamicSharedMemorySize,
                         (int)sizeof(AttnSmem));

    qkv_kernel<<<dim3(N_TOK / 128, F3 / 128, B_SZ), 256>>>(x, qkv_w, qkv_b);
    attn_kernel<<<dim3(N_TOK / QROWS, B_SZ), 512, sizeof(AttnSmem)>>>();
    out_kernel<<<dim3(N_TOK / 128, EDIM / 128, B_SZ), 256>>>(x, out_w, out_b, out);
}

// round 17
// speedup vs baseline: 8.9618x; 1.0050x over previous
#include <cuda_runtime.h>
#include <cuda_fp16.h>
#include <math.h>
#include <stdint.h>

#define B_SZ   4
#define EDIM   256
#define N_TOK  4096
#define F3     768
#define SCL    0.0625f   // 1/sqrt(256)
#define LOG2E  1.4426950408889634f

// Scratch (allocation-free rule: __device__ globals)
__device__ __align__(16) __half g_qkvh[(size_t)B_SZ * N_TOK * F3]; // [b, n, 3E]

__device__ __forceinline__ void ldsm_x4(uint32_t& r0, uint32_t& r1, uint32_t& r2, uint32_t& r3,
                                        uint32_t addr) {
    asm volatile("ldmatrix.sync.aligned.m8n8.x4.shared.b16 {%0,%1,%2,%3}, [%4];"
                 : "=r"(r0), "=r"(r1), "=r"(r2), "=r"(r3) : "r"(addr));
}
__device__ __forceinline__ void ldsm_x4_t(uint32_t& r0, uint32_t& r1, uint32_t& r2, uint32_t& r3,
                                          uint32_t addr) {
    asm volatile("ldmatrix.sync.aligned.m8n8.x4.trans.shared.b16 {%0,%1,%2,%3}, [%4];"
                 : "=r"(r0), "=r"(r1), "=r"(r2), "=r"(r3) : "r"(addr));
}
__device__ __forceinline__ void mma_f16(float c[4], uint32_t a0, uint32_t a1, uint32_t a2,
                                        uint32_t a3, uint32_t b0, uint32_t b1) {
    asm volatile(
        "mma.sync.aligned.m16n8k16.row.col.f32.f16.f16.f32 "
        "{%0,%1,%2,%3}, {%4,%5,%6,%7}, {%8,%9}, {%0,%1,%2,%3};\n"
        : "+f"(c[0]), "+f"(c[1]), "+f"(c[2]), "+f"(c[3])
        : "r"(a0), "r"(a1), "r"(a2), "r"(a3), "r"(b0), "r"(b1));
}
__device__ __forceinline__ uint32_t sptr(const void* p) {
    return (uint32_t)__cvta_generic_to_shared(p);
}
// pack (lo, hi) floats into f16x2 (lo in low half). cvt d,a,b: a->high, b->low
__device__ __forceinline__ uint32_t h2pack(float lo, float hi) {
    uint32_t r;
    asm("cvt.rn.f16x2.f32 %0, %1, %2;" : "=r"(r) : "f"(hi), "f"(lo));
    return r;
}
// packed exp2 on two fp16 values
__device__ __forceinline__ uint32_t ex2h2(uint32_t x) {
    uint32_t r;
    asm("ex2.approx.f16x2 %0, %1;" : "=r"(r) : "r"(x));
    return r;
}
__device__ __forceinline__ float2 h22f2(uint32_t p) {
    __half2 h = *reinterpret_cast<__half2*>(&p);
    return __half22float2(h);
}
__device__ __forceinline__ void cp16(uint32_t dst, const void* src) {
    asm volatile("cp.async.cg.shared.global [%0], [%1], 16;" :: "r"(dst), "l"(src));
}
#define CP_COMMIT() asm volatile("cp.async.commit_group;")
#define CP_WAIT(n)  asm volatile("cp.async.wait_group %0;" :: "n"(n))

#define XS_STRIDE 136   // 272B % 128 == 16 -> conflict-free ldsm
#define KS_STRIDE 72    // 144B % 128 == 16

// ---------------------------------------------------------------------------
// Kernel 1: qkv[b, m, f] = sum_e x[b, e, m] * w[f, e] + bias[f]   (f16 mma)
// ---------------------------------------------------------------------------
__global__ __launch_bounds__(256, 2) void qkv_kernel(const float* __restrict__ x,
                                                     const float* __restrict__ w,
                                                     const float* __restrict__ bias) {
    __shared__ __half Xs[64][XS_STRIDE];    // [e][m]
    __shared__ __half Ws[128][KS_STRIDE];   // [f][e]
    const int tid  = threadIdx.x;
    const int lane = tid & 31;
    const int wp   = tid >> 5;
    const int g    = lane >> 2;
    const int t    = lane & 3;
    const int wm   = wp >> 1;
    const int wf   = wp & 1;
    const int mbase = blockIdx.x * 128;
    const int fbase = blockIdx.y * 128;
    const int b     = blockIdx.z;
    const float* xb = x + (size_t)b * EDIM * N_TOK;

    float c[2][8][4];
#pragma unroll
    for (int i = 0; i < 2; i++)
#pragma unroll
        for (int j = 0; j < 8; j++)
#pragma unroll
            for (int q = 0; q < 4; q++) c[i][j][q] = 0.f;

    const int at_row = (lane >> 4) * 8 + (lane & 7);
    const int at_col = ((lane >> 3) & 1) * 8;
    const int bk_row = wf * 64 + ((lane >> 4) & 1) * 8 + (lane & 7);
    const int bk_col = ((lane >> 3) & 1) * 8;

    for (int e0 = 0; e0 < EDIM; e0 += 64) {
        __syncthreads();
#pragma unroll
        for (int i = 0; i < 8; i++) {
            int lin = tid + i * 256;
            int e = lin >> 5, m4 = (lin & 31) * 4;
            float4 v = *(const float4*)(xb + (size_t)(e0 + e) * N_TOK + mbase + m4);
            uint32_t p0 = h2pack(v.x, v.y), p1 = h2pack(v.z, v.w);
            *(uint2*)(&Xs[e][m4]) = make_uint2(p0, p1);
        }
#pragma unroll
        for (int i = 0; i < 8; i++) {
            int lin = tid + i * 256;
            int f = lin >> 4, e4 = (lin & 15) * 4;
            float4 v = *(const float4*)(w + (size_t)(fbase + f) * EDIM + e0 + e4);
            uint32_t p0 = h2pack(v.x, v.y), p1 = h2pack(v.z, v.w);
            *(uint2*)(&Ws[f][e4]) = make_uint2(p0, p1);
        }
        __syncthreads();

#pragma unroll
        for (int ks = 0; ks < 4; ks++) {
            uint32_t a[2][4];
#pragma unroll
            for (int mi = 0; mi < 2; mi++)
                ldsm_x4_t(a[mi][0], a[mi][1], a[mi][2], a[mi][3],
                          sptr(&Xs[ks * 16 + at_row][wm * 32 + mi * 16 + at_col]));
#pragma unroll
            for (int p = 0; p < 4; p++) {
                uint32_t b0, b1, b2, b3;
                ldsm_x4(b0, b1, b2, b3, sptr(&Ws[bk_row + p * 16][ks * 16 + bk_col]));
#pragma unroll
                for (int mi = 0; mi < 2; mi++) {
                    mma_f16(c[mi][2 * p],     a[mi][0], a[mi][1], a[mi][2], a[mi][3], b0, b1);
                    mma_f16(c[mi][2 * p + 1], a[mi][0], a[mi][1], a[mi][2], a[mi][3], b2, b3);
                }
            }
        }
    }

#pragma unroll
    for (int ni = 0; ni < 8; ni++) {
        int f = fbase + wf * 64 + ni * 8 + 2 * t;
        float2 bb = *(const float2*)(bias + f);
#pragma unroll
        for (int mi = 0; mi < 2; mi++) {
            int m0 = mbase + wm * 32 + mi * 16 + g;
            uint32_t ptop = h2pack(c[mi][ni][0] + bb.x, c[mi][ni][1] + bb.y);
            uint32_t pbot = h2pack(c[mi][ni][2] + bb.x, c[mi][ni][3] + bb.y);
            *(uint32_t*)(&g_qkvh[((size_t)b * N_TOK + m0) * F3 + f])     = ptop;
            *(uint32_t*)(&g_qkvh[((size_t)b * N_TOK + m0 + 8) * F3 + f]) = pbot;
        }
    }
}

// ---------------------------------------------------------------------------
// Kernel 2: flash attention + FUSED out-projection/residual.
// Main loop identical to R15 best. Epilogue: o -> smem (fp16), then
// out[e,m] = x + out_w @ o^T + out_b computed in-CTA (warp = 64e x 32m).
// ---------------------------------------------------------------------------
#define QS_STRIDE 264   // f16, 528B row, %128 == 16 -> conflict-free ldsm
#define QROWS 128

struct AttnSmem {
    __half Qs[QROWS][QS_STRIDE];    // Q; epilogue: o (fp16) [m][k]
    __half Ks[64][QS_STRIDE];       // K; epilogue: W chunk [256][72] (spans into Vs)
    __half Vs[64][QS_STRIDE];
    __half Ps[QROWS][KS_STRIDE];
    float Mred[QROWS][2];
    float Lred[QROWS][2];
    float m_s[QROWS], l_s[QROWS], scr[QROWS];
};

__global__ __launch_bounds__(512, 1) void attn_kernel(const float* __restrict__ x,
                                                      const float* __restrict__ ow,
                                                      const float* __restrict__ ob,
                                                      float* __restrict__ out) {
    extern __shared__ char smem_raw[];
    AttnSmem& S = *reinterpret_cast<AttnSmem*>(smem_raw);

    const int tid  = threadIdx.x;
    const int lane = tid & 31;
    const int w    = tid >> 5;
    const int g    = lane >> 2;
    const int t    = lane & 3;
    const int rt16 = (w & 7) * 16;      // S-phase row tile
    const int half = w >> 3;            // S-phase k half
    const int rt2  = w & 3;             // PV row group (32 rows)
    const int dq   = w >> 2;            // PV d quarter (64 cols)
    const int qbase = blockIdx.x * QROWS;
    const int b     = blockIdx.y;
    const __half* qkv = g_qkvh + (size_t)b * N_TOK * F3;

    const int top = rt16 + g, bot = rt16 + g + 8;

    // ---- prologue: issue K_0 ----
#pragma unroll
    for (int i = 0; i < 4; i++) {
        int c = tid + i * 512;
        int row = c >> 5, col = (c & 31) * 8;
        cp16(sptr(&S.Ks[row][col]), qkv + (size_t)row * F3 + 256 + col);
    }
    CP_COMMIT();

    // ---- load Q tile [128][256] ----
    {
        const int ldrow = tid >> 2, ldq4 = tid & 3;
#pragma unroll
        for (int i = 0; i < 8; i++) {
            int col = ldq4 * 64 + i * 8;
            uint4 v = *(const uint4*)(qkv + (size_t)(qbase + ldrow) * F3 + col);
            *(uint4*)(&S.Qs[ldrow][col]) = v;
        }
    }
    if (tid < QROWS) { S.m_s[tid] = -INFINITY; S.l_s[tid] = 0.f; }

    float cO[2][8][4];
#pragma unroll
    for (int mi = 0; mi < 2; mi++)
#pragma unroll
        for (int i = 0; i < 8; i++)
#pragma unroll
            for (int j = 0; j < 4; j++) cO[mi][i][j] = 0.f;

    const int a_row   = rt16 + (lane & 15);
    const int a_coff  = (lane >> 4) * 8;
    const int bk_row  = half * 32 + ((lane >> 4) & 1) * 8 + (lane & 7);
    const int bk_coff = ((lane >> 3) & 1) * 8;
    const int pv_arow = rt2 * 32 + (lane & 15);
    const int bv_krow = ((lane >> 3) & 1) * 8 + (lane & 7);
    const int bv_doff = (lane >> 4) * 8;

    for (int kb = 0; kb < N_TOK; kb += 64) {
        CP_WAIT(0);
        __syncthreads();

        // issue V_i
#pragma unroll
        for (int i = 0; i < 4; i++) {
            int c = tid + i * 512;
            int row = c >> 5, col = (c & 31) * 8;
            cp16(sptr(&S.Vs[row][col]), qkv + (size_t)(kb + row) * F3 + 512 + col);
        }
        CP_COMMIT();

        // ---- S = Q K^T ----
        float cS[4][4];
#pragma unroll
        for (int n = 0; n < 4; n++)
#pragma unroll
            for (int j = 0; j < 4; j++) cS[n][j] = 0.f;

#pragma unroll
        for (int dc = 0; dc < 4; dc++) {
#pragma unroll
            for (int ks = 0; ks < 4; ks++) {
                int d0 = dc * 64 + ks * 16;
                uint32_t a0, a1, a2, a3;
                ldsm_x4(a0, a1, a2, a3, sptr(&S.Qs[a_row][d0 + a_coff]));
#pragma unroll
                for (int p = 0; p < 2; p++) {
                    uint32_t b0, b1, b2, b3;
                    ldsm_x4(b0, b1, b2, b3, sptr(&S.Ks[bk_row + p * 16][d0 + bk_coff]));
                    mma_f16(cS[2 * p],     a0, a1, a2, a3, b0, b1);
                    mma_f16(cS[2 * p + 1], a0, a1, a2, a3, b2, b3);
                }
            }
        }

        __syncthreads();   // K buffer free

        // issue K_{i+1}
        {
            int kb2 = (kb + 64) & (N_TOK - 1);
#pragma unroll
            for (int i = 0; i < 4; i++) {
                int c = tid + i * 512;
                int row = c >> 5, col = (c & 31) * 8;
                cp16(sptr(&S.Ks[row][col]), qkv + (size_t)(kb2 + row) * F3 + 256 + col);
            }
            CP_COMMIT();
        }

        // ---- softmax (packed f16x2 exp2) ----
        float mt = -INFINITY, mb = -INFINITY;
#pragma unroll
        for (int nt = 0; nt < 4; nt++) {
            cS[nt][0] *= SCL; cS[nt][1] *= SCL; cS[nt][2] *= SCL; cS[nt][3] *= SCL;
            mt = fmaxf(mt, fmaxf(cS[nt][0], cS[nt][1]));
            mb = fmaxf(mb, fmaxf(cS[nt][2], cS[nt][3]));
        }
        mt = fmaxf(mt, __shfl_xor_sync(0xffffffffu, mt, 1));
        mt = fmaxf(mt, __shfl_xor_sync(0xffffffffu, mt, 2));
        mb = fmaxf(mb, __shfl_xor_sync(0xffffffffu, mb, 1));
        mb = fmaxf(mb, __shfl_xor_sync(0xffffffffu, mb, 2));
        if (t == 0) { S.Mred[top][half] = mt; S.Mred[bot][half] = mb; }
        __syncthreads();

        float mwt = fmaxf(S.Mred[top][0], S.Mred[top][1]);
        float mwb = fmaxf(S.Mred[bot][0], S.Mred[bot][1]);
        float moldt = S.m_s[top], moldb = S.m_s[bot];
        float mnt = fmaxf(moldt, mwt), mnb = fmaxf(moldb, mwb);
        float sct = __expf(moldt - mnt), scb = __expf(moldb - mnb);
        float mlt = mnt * LOG2E, mlb = mnb * LOG2E;
        float st = 0.f, sb = 0.f;
#pragma unroll
        for (int nt = 0; nt < 4; nt++) {
            int col = half * 32 + nt * 8 + 2 * t;
            float a0 = fmaf(cS[nt][0], LOG2E, -mlt);
            float a1 = fmaf(cS[nt][1], LOG2E, -mlt);
            uint32_t pt = ex2h2(h2pack(a0, a1));
            *(uint32_t*)(&S.Ps[top][col]) = pt;
            float2 ft = h22f2(pt);
            st += ft.x + ft.y;
            float a2 = fmaf(cS[nt][2], LOG2E, -mlb);
            float a3 = fmaf(cS[nt][3], LOG2E, -mlb);
            uint32_t pb = ex2h2(h2pack(a2, a3));
            *(uint32_t*)(&S.Ps[bot][col]) = pb;
            float2 fb = h22f2(pb);
            sb += fb.x + fb.y;
        }
        st += __shfl_xor_sync(0xffffffffu, st, 1);
        st += __shfl_xor_sync(0xffffffffu, st, 2);
        sb += __shfl_xor_sync(0xffffffffu, sb, 1);
        sb += __shfl_xor_sync(0xffffffffu, sb, 2);
        if (t == 0) {
            S.Lred[top][half] = st; S.Lred[bot][half] = sb;
            S.scr[top] = sct;       S.scr[bot] = scb;
        }

        CP_WAIT(1);
        __syncthreads();

        if (half == 0 && t == 0) {
            S.m_s[top] = mnt;
            S.l_s[top] = S.l_s[top] * sct + S.Lred[top][0] + S.Lred[top][1];
            S.m_s[bot] = mnb;
            S.l_s[bot] = S.l_s[bot] * scb + S.Lred[bot][0] + S.Lred[bot][1];
        }

        // ---- PV ----
        {
            float s00 = S.scr[rt2 * 32 + g],      s01 = S.scr[rt2 * 32 + g + 8];
            float s10 = S.scr[rt2 * 32 + 16 + g], s11 = S.scr[rt2 * 32 + 16 + g + 8];
#pragma unroll
            for (int ni = 0; ni < 8; ni++) {
                cO[0][ni][0] *= s00; cO[0][ni][1] *= s00;
                cO[0][ni][2] *= s01; cO[0][ni][3] *= s01;
                cO[1][ni][0] *= s10; cO[1][ni][1] *= s10;
                cO[1][ni][2] *= s11; cO[1][ni][3] *= s11;
            }
        }
#pragma unroll
        for (int ks = 0; ks < 4; ks++) {
            uint32_t a[2][4];
#pragma unroll
            for (int mi = 0; mi < 2; mi++)
                ldsm_x4(a[mi][0], a[mi][1], a[mi][2], a[mi][3],
                        sptr(&S.Ps[pv_arow + mi * 16][ks * 16 + a_coff]));
#pragma unroll
            for (int p = 0; p < 4; p++) {
                uint32_t b0, b1, b2, b3;
                ldsm_x4_t(b0, b1, b2, b3,
                          sptr(&S.Vs[ks * 16 + bv_krow][dq * 64 + p * 16 + bv_doff]));
#pragma unroll
                for (int mi = 0; mi < 2; mi++) {
                    mma_f16(cO[mi][2 * p],     a[mi][0], a[mi][1], a[mi][2], a[mi][3], b0, b1);
                    mma_f16(cO[mi][2 * p + 1], a[mi][0], a[mi][1], a[mi][2], a[mi][3], b2, b3);
                }
            }
        }
    }

    CP_WAIT(0);        // drain trailing K prefetch before reusing Ks region
    __syncthreads();   // final l_s visible; Qs/Ks/Vs dead

    // ---- epilogue part 1: normalized o (fp16) -> Osm (reuse Qs region) ----
    __half (*Osm)[QS_STRIDE] = S.Qs;   // [m 0..127][k 0..255]
#pragma unroll
    for (int mi = 0; mi < 2; mi++) {
        int r0 = rt2 * 32 + mi * 16 + g;
        float inv0 = 1.f / S.l_s[r0];
        float inv1 = 1.f / S.l_s[r0 + 8];
#pragma unroll
        for (int ni = 0; ni < 8; ni++) {
            int col = dq * 64 + ni * 8 + 2 * t;
            *(uint32_t*)(&Osm[r0][col]) =
                h2pack(cO[mi][ni][0] * inv0, cO[mi][ni][1] * inv0);
            *(uint32_t*)(&Osm[r0 + 8][col]) =
                h2pack(cO[mi][ni][2] * inv1, cO[mi][ni][3] * inv1);
        }
    }

    // ---- epilogue part 2: out[e][m] = x + out_w @ o^T + out_b ----
    {
        __half (*Wsm)[KS_STRIDE] = reinterpret_cast<__half(*)[KS_STRIDE]>(&S.Ks[0][0]);
        const int eg = w & 3;           // 64-e group
        const int mg = w >> 2;          // 32-m group
        const int ae_row = eg * 64 + (lane & 15);
        const int ae_off = (lane >> 4) * 8;
        const int bm_row = mg * 32 + ((lane >> 4) & 1) * 8 + (lane & 7);
        const int bm_off = ((lane >> 3) & 1) * 8;

        float cc[4][4][4];
#pragma unroll
        for (int i = 0; i < 4; i++)
#pragma unroll
            for (int j = 0; j < 4; j++)
#pragma unroll
                for (int q = 0; q < 4; q++) cc[i][j][q] = 0.f;

        for (int k0 = 0; k0 < EDIM; k0 += 64) {
            __syncthreads();   // Wsm reuse / Osm ready (first iter)
            // load W chunk [256 e][64 k] fp32 -> fp16
#pragma unroll
            for (int i = 0; i < 8; i++) {
                int lin = tid + i * 512;
                int e = lin >> 4, k4 = (lin & 15) * 4;
                float4 v = *(const float4*)(ow + (size_t)e * EDIM + k0 + k4);
                uint32_t p0 = h2pack(v.x, v.y), p1 = h2pack(v.z, v.w);
                *(uint2*)(&Wsm[e][k4]) = make_uint2(p0, p1);
            }
            __syncthreads();

#pragma unroll
            for (int ks = 0; ks < 4; ks++) {
                uint32_t a[4][4];
#pragma unroll
                for (int et = 0; et < 4; et++)
                    ldsm_x4(a[et][0], a[et][1], a[et][2], a[et][3],
                            sptr(&Wsm[ae_row + et * 16][ks * 16 + ae_off]));
#pragma unroll
                for (int p = 0; p < 2; p++) {
                    uint32_t b0, b1, b2, b3;
                    ldsm_x4(b0, b1, b2, b3,
                            sptr(&Osm[bm_row + p * 16][k0 + ks * 16 + bm_off]));
#pragma unroll
                    for (int et = 0; et < 4; et++) {
                        mma_f16(cc[et][2 * p],     a[et][0], a[et][1], a[et][2], a[et][3], b0, b1);
                        mma_f16(cc[et][2 * p + 1], a[et][0], a[et][1], a[et][2], a[et][3], b2, b3);
                    }
                }
            }
        }

        // residual + bias, fp32 out [e][m]
        size_t bE = (size_t)b * EDIM;
#pragma unroll
        for (int et = 0; et < 4; et++) {
            int e0 = eg * 64 + et * 16 + g;
            float bt = ob[e0], bb2 = ob[e0 + 8];
#pragma unroll
            for (int nt = 0; nt < 4; nt++) {
                int m = qbase + mg * 32 + nt * 8 + 2 * t;
                size_t it = (bE + e0) * N_TOK + m;
                size_t ib = (bE + e0 + 8) * N_TOK + m;
                float2 xt = *(const float2*)(x + it);
                float2 xb = *(const float2*)(x + ib);
                *(float2*)(out + it) = make_float2(xt.x + cc[et][nt][0] + bt,
                                                   xt.y + cc[et][nt][1] + bt);
                *(float2*)(out + ib) = make_float2(xb.x + cc[et][nt][2] + bb2,
                                                   xb.y + cc[et][nt][3] + bb2);
            }
        }
    }
}

// ---------------------------------------------------------------------------
extern "C" void kernel_launch(void* const* d_in, const int* in_sizes, int n_in,
                              void* d_out, int out_size) {
    const float* x = nullptr; const float* qkv_w = nullptr; const float* qkv_b = nullptr;
    const float* out_w = nullptr; const float* out_b = nullptr;
    for (int i = 0; i < n_in; i++) {
        switch (in_sizes[i]) {
            case 4194304: x     = (const float*)d_in[i]; break;
            case  196608: qkv_w = (const float*)d_in[i]; break;
            case     768: qkv_b = (const float*)d_in[i]; break;
            case   65536: out_w = (const float*)d_in[i]; break;
            case     256: out_b = (const float*)d_in[i]; break;
            default: break;
        }
    }
    float* out = (float*)d_out;

    cudaFuncSetAttribute(attn_kernel, cudaFuncAttributeMaxDynamicSharedMemorySize,
                         (int)sizeof(AttnSmem));

    qkv_kernel<<<dim3(N_TOK / 128, F3 / 128, B_SZ), 256>>>(x, qkv_w, qkv_b);
    attn_kernel<<<dim3(N_TOK / QROWS, B_SZ), 512, sizeof(AttnSmem)>>>(x, out_w, out_b, out);
}